// round 13
// baseline (speedup 1.0000x reference)
#include <cuda_runtime.h>
#include <cuda_fp16.h>
#include <math.h>
#include <stdint.h>

#define Bb 2
#define Nn 2048
#define EMB 768
#define NH 12
#define DH 64
#define DEPTH 6
#define FF 3072
#define TOK (Bb * Nn)  // 4096
#define QKVW (3 * EMB) // 2304
#define LN_EPS 1e-6f

// ---------------- scratch (static device globals) ---------------------------
__device__ float g_h[TOK * EMB];
__device__ __half g_y[TOK * EMB];
__device__ __half g_qkv[TOK * 3 * EMB];
__device__ __half g_o[TOK * EMB];
__device__ __half g_mid[TOK * FF];
__device__ __half g_wqkv[DEPTH * EMB * 3 * EMB];
__device__ __half g_wo[DEPTH * EMB * EMB];
__device__ __half g_w1[DEPTH * EMB * FF];
__device__ __half g_w2[DEPTH * FF * EMB];

__constant__ float c_slopes[NH] = {
    0.5f, 0.25f, 0.125f, 0.0625f, 0.03125f, 0.015625f, 0.0078125f, 0.00390625f,
    0.70710678118654752f, 0.35355339059327376f, 0.17677669529663688f,
    0.08838834764831844f};

__device__ __forceinline__ void cp16(uint32_t dst, const void* src) {
    asm volatile("cp.async.cg.shared.global [%0], [%1], 16;" ::"r"(dst),
                 "l"(src));
}

__device__ __forceinline__ uint32_t packh2(float a, float b) {
    __half2 h = __floats2half2_rn(a, b);
    return *(uint32_t*)&h;
}

#define MMA_FP16(d, a, b)                                                     \
    asm volatile(                                                             \
        "mma.sync.aligned.m16n8k16.row.col.f32.f16.f16.f32 "                  \
        "{%0,%1,%2,%3},{%4,%5,%6,%7},{%8,%9},{%0,%1,%2,%3};"                  \
        : "+f"(d[0]), "+f"(d[1]), "+f"(d[2]), "+f"(d[3])                      \
        : "r"(a[0]), "r"(a[1]), "r"(a[2]), "r"(a[3]), "r"(b[0]), "r"(b[1]))

#define LDSM_X4(r0, r1, r2, r3, addr)                                        \
    asm volatile(                                                            \
        "ldmatrix.sync.aligned.m8n8.x4.shared.b16 {%0,%1,%2,%3}, [%4];"      \
        : "=r"(r0), "=r"(r1), "=r"(r2), "=r"(r3)                             \
        : "r"(addr))

#define LDSM_X4_T(r0, r1, r2, r3, addr)                                      \
    asm volatile(                                                            \
        "ldmatrix.sync.aligned.m8n8.x4.trans.shared.b16 {%0,%1,%2,%3}, "     \
        "[%4];"                                                              \
        : "=r"(r0), "=r"(r1), "=r"(r2), "=r"(r3)                             \
        : "r"(addr))

// ---------------- copy x -> h ------------------------------------------------
__global__ void copy_kernel(const float* __restrict__ x) {
    int i = blockIdx.x * blockDim.x + threadIdx.x;
    if (i < TOK * EMB) g_h[i] = x[i];
}

// ---------------- fused transpose + fp16 convert of ALL weights -------------
#define TQKV (72 * 24 * DEPTH)
#define TWO (24 * 24 * DEPTH)
#define TW1 (96 * 24 * DEPTH)
#define TW2 (24 * 96 * DEPTH)
#define TALL (TQKV + TWO + TW1 + TW2)

__global__ void transpose_half_all(const float* __restrict__ wqkv,
                                   const float* __restrict__ wo,
                                   const float* __restrict__ w1,
                                   const float* __restrict__ w2,
                                   __half* __restrict__ pwqkv,
                                   __half* __restrict__ pwo,
                                   __half* __restrict__ pw1,
                                   __half* __restrict__ pw2) {
    __shared__ float tile[32][33];
    int b = blockIdx.x;
    const float* W;
    __half* Wt;
    int K, N;
    if (b < TQKV) {
        W = wqkv; Wt = pwqkv; K = EMB; N = 3 * EMB;
    } else if (b < TQKV + TWO) {
        b -= TQKV; W = wo; Wt = pwo; K = EMB; N = EMB;
    } else if (b < TQKV + TWO + TW1) {
        b -= TQKV + TWO; W = w1; Wt = pw1; K = EMB; N = FF;
    } else {
        b -= TQKV + TWO + TW1; W = w2; Wt = pw2; K = FF; N = EMB;
    }
    int ntiles = N / 32, tpl = ntiles * (K / 32);
    int layer = b / tpl, rem = b % tpl;
    int bn = (rem % ntiles) * 32, bk = (rem / ntiles) * 32;
    W += (size_t)layer * K * N;
    Wt += (size_t)layer * K * N;
    int tx = threadIdx.x, ty = threadIdx.y;
#pragma unroll
    for (int i = 0; i < 32; i += 8)
        tile[ty + i][tx] = W[(size_t)(bk + ty + i) * N + bn + tx];
    __syncthreads();
#pragma unroll
    for (int i = 0; i < 32; i += 8)
        Wt[(size_t)(bn + ty + i) * K + bk + tx] =
            __float2half_rn(tile[tx][ty + i]);
}

// ---------------- LayerNorm (float in; float or half out) -------------------
__global__ void ln_kernel(const float* __restrict__ in,
                          const float* __restrict__ scale,
                          const float* __restrict__ bias, void* __restrict__ o,
                          int half_out) {
    int row = blockIdx.x;
    const float* p = in + (size_t)row * EMB;
    float s = 0.f, ss = 0.f;
    for (int i = threadIdx.x; i < EMB; i += 256) {
        float v = p[i];
        s += v;
        ss += v * v;
    }
#pragma unroll
    for (int of = 16; of; of >>= 1) {
        s += __shfl_xor_sync(0xffffffffu, s, of);
        ss += __shfl_xor_sync(0xffffffffu, ss, of);
    }
    __shared__ float sh_s[8], sh_ss[8];
    int w = threadIdx.x >> 5, lane = threadIdx.x & 31;
    if (lane == 0) { sh_s[w] = s; sh_ss[w] = ss; }
    __syncthreads();
    if (threadIdx.x < 32) {
        s = (lane < 8) ? sh_s[lane] : 0.f;
        ss = (lane < 8) ? sh_ss[lane] : 0.f;
#pragma unroll
        for (int of = 4; of; of >>= 1) {
            s += __shfl_xor_sync(0xffffffffu, s, of);
            ss += __shfl_xor_sync(0xffffffffu, ss, of);
        }
        if (lane == 0) { sh_s[0] = s; sh_ss[0] = ss; }
    }
    __syncthreads();
    float mean = sh_s[0] * (1.0f / EMB);
    float var = sh_ss[0] * (1.0f / EMB) - mean * mean;
    float inv = rsqrtf(var + LN_EPS);
    if (half_out) {
        __half* q = (__half*)o + (size_t)row * EMB;
        for (int i = threadIdx.x; i < EMB; i += 256)
            q[i] = __float2half_rn((p[i] - mean) * inv * scale[i] + bias[i]);
    } else {
        float* q = (float*)o + (size_t)row * EMB;
        for (int i = threadIdx.x; i < EMB; i += 256)
            q[i] = (p[i] - mean) * inv * scale[i] + bias[i];
    }
}

#define FLAG_BIAS 1
#define FLAG_GELU 2
#define FLAG_ADD 4
#define FLAG_HALF 8

__device__ __forceinline__ float gelu_tanh(float x) {
    const float k0 = 0.7978845608028654f;
    return 0.5f * x * (1.0f + tanhf(k0 * (x + 0.044715f * x * x * x)));
}

// ======== fp16 GEMM, KT=64 (128B rows, attention-validated layout) ==========
// A rows / B rows are 64 halves = 128B, swizzle chunk c -> c ^ (row & 7).
// Frag offsets: ((2*kc + cbit) ^ row7) << 4, kc = 0..3 (K=64 per stage).

// ---------------- gemm64: CTA 128x64, 128 thr, 3 stages, 3 CTA/SM -----------
#define G64_STAGE (16384 + 8192)             // A 128x128B + B 64x128B
#define GEMM_SMEM_64 (3 * G64_STAGE)         // 72KB

__global__ __launch_bounds__(128, 3) void gemm64(
    const __half* __restrict__ A, const __half* __restrict__ Wt,
    const float* __restrict__ bias, void* __restrict__ Cv, int K, int Nout,
    int flags) {
    extern __shared__ char smem[];
    const uint32_t sb = (uint32_t)__cvta_generic_to_shared(smem);
    const int tid = threadIdx.x;
    const int warp = tid >> 5, lane = tid & 31;
    const int wm = warp >> 1, wn = warp & 1;
    const int bm = blockIdx.y * 128, bn = blockIdx.x * 64;

    // staging: A full row per thread (8 chunks); B row tid>>1, half (tid&1)
    const __half* gA = A + (size_t)(bm + tid) * K;
    uint32_t stA[8];
#pragma unroll
    for (int c = 0; c < 8; c++)
        stA[c] = sb + (uint32_t)tid * 128 + (((uint32_t)(c ^ (tid & 7))) << 4);
    const int brow = tid >> 1, bc0 = (tid & 1) * 4;
    const __half* gB = Wt + (size_t)(bn + brow) * K + bc0 * 8;
    uint32_t stB[4];
#pragma unroll
    for (int i = 0; i < 4; i++)
        stB[i] = sb + 16384 + (uint32_t)brow * 128 +
                 (((uint32_t)((bc0 + i) ^ (brow & 7))) << 4);

#define LOAD_S64(s, t_)                                                    \
    do {                                                                   \
        const __half* _a = gA + (t_) * 64;                                 \
        const __half* _b = gB + (t_) * 64;                                 \
        uint32_t _so = (uint32_t)(s)*G64_STAGE;                            \
        _Pragma("unroll") for (int _c = 0; _c < 8; _c++)                   \
            cp16(stA[_c] + _so, _a + _c * 8);                              \
        _Pragma("unroll") for (int _i = 0; _i < 4; _i++)                   \
            cp16(stB[_i] + _so, _b + _i * 8);                              \
        asm volatile("cp.async.commit_group;");                            \
    } while (0)

    const int arow7 = lane & 7;
    const int a8 = ((lane >> 3) & 1) * 8;
    const int acbit = lane >> 4;
    uint32_t aBase[4];
#pragma unroll
    for (int mf = 0; mf < 4; mf++)
        aBase[mf] = sb + (uint32_t)(wm * 64 + mf * 16 + arow7 + a8) * 128;
    uint32_t aoff[4];
#pragma unroll
    for (int kc = 0; kc < 4; kc++)
        aoff[kc] = ((uint32_t)((2 * kc + acbit) ^ arow7)) << 4;

    const int brow7 = lane & 7;
    const int bn8 = (lane >> 4) * 8;
    const int bcb = (lane >> 3) & 1;
    uint32_t bBase[2];
#pragma unroll
    for (int p = 0; p < 2; p++)
        bBase[p] =
            sb + 16384 + (uint32_t)(wn * 32 + p * 16 + brow7 + bn8) * 128;
    uint32_t boff[4];
#pragma unroll
    for (int kc = 0; kc < 4; kc++)
        boff[kc] = ((uint32_t)((2 * kc + bcb) ^ brow7)) << 4;

    float acc[4][4][4];
#pragma unroll
    for (int i = 0; i < 4; i++)
#pragma unroll
        for (int j = 0; j < 4; j++)
#pragma unroll
            for (int c = 0; c < 4; c++) acc[i][j][c] = 0.f;

    const int T = K / 64;
    LOAD_S64(0, 0);
    LOAD_S64(1, 1);

    int s = 0;
    for (int t = 0; t < T; t++) {
        if (t + 1 < T)
            asm volatile("cp.async.wait_group 1;");
        else
            asm volatile("cp.async.wait_group 0;");
        __syncthreads();
        if (t + 2 < T) LOAD_S64((s + 2) % 3, t + 2);

        uint32_t so = (uint32_t)s * G64_STAGE;
#pragma unroll
        for (int kc = 0; kc < 4; kc++) {
            uint32_t af[4][4];
#pragma unroll
            for (int mf = 0; mf < 4; mf++)
                LDSM_X4(af[mf][0], af[mf][1], af[mf][2], af[mf][3],
                        aBase[mf] + so + aoff[kc]);
#pragma unroll
            for (int p = 0; p < 2; p++) {
                uint32_t bf0[2], bf1[2];
                LDSM_X4(bf0[0], bf0[1], bf1[0], bf1[1],
                        bBase[p] + so + boff[kc]);
#pragma unroll
                for (int mf = 0; mf < 4; mf++) {
                    MMA_FP16(acc[mf][2 * p], af[mf], bf0);
                    MMA_FP16(acc[mf][2 * p + 1], af[mf], bf1);
                }
            }
        }
        s = (s + 1) % 3;
    }

    int r = lane >> 2, kq = lane & 3;
#pragma unroll
    for (int mf = 0; mf < 4; mf++) {
#pragma unroll
        for (int nf = 0; nf < 4; nf++) {
            int n0 = bn + wn * 32 + nf * 8 + kq * 2;
#pragma unroll
            for (int half = 0; half < 2; half++) {
                int m0 = bm + wm * 64 + mf * 16 + r + half * 8;
                float2 v;
                v.x = acc[mf][nf][half * 2 + 0];
                v.y = acc[mf][nf][half * 2 + 1];
                if (flags & FLAG_BIAS) {
                    v.x += bias[n0];
                    v.y += bias[n0 + 1];
                }
                if (flags & FLAG_GELU) {
                    v.x = gelu_tanh(v.x);
                    v.y = gelu_tanh(v.y);
                }
                if (flags & FLAG_HALF) {
                    __half2* dst =
                        (__half2*)((__half*)Cv + (size_t)m0 * Nout + n0);
                    *dst = __floats2half2_rn(v.x, v.y);
                } else {
                    float2* dst =
                        (float2*)((float*)Cv + (size_t)m0 * Nout + n0);
                    if (flags & FLAG_ADD) {
                        float2 old = *dst;
                        v.x += old.x;
                        v.y += old.y;
                    }
                    *dst = v;
                }
            }
        }
    }
}

// ---------------- gemm128: CTA 128x128, 256 thr (8 warps), 3 st, 2 CTA/SM ---
#define G128_STAGE (16384 + 16384)
#define GEMM_SMEM_128 (3 * G128_STAGE)  // 96KB

__global__ __launch_bounds__(256, 2) void gemm128(
    const __half* __restrict__ A, const __half* __restrict__ Wt,
    const float* __restrict__ bias, void* __restrict__ Cv, int K, int Nout,
    int flags) {
    extern __shared__ char smem[];
    const uint32_t sb = (uint32_t)__cvta_generic_to_shared(smem);
    const int tid = threadIdx.x;
    const int warp = tid >> 5, lane = tid & 31;
    const int wm = warp >> 2, wn = warp & 3;  // 2m x 4n
    const int bm = blockIdx.y * 128, bn = blockIdx.x * 128;

    // staging: 256 threads; each does half of an A row + half of a B row
    const int srow = tid >> 1, c0 = (tid & 1) * 4;
    const int sxor = srow & 7;
    const __half* gA = A + (size_t)(bm + srow) * K + c0 * 8;
    const __half* gB = Wt + (size_t)(bn + srow) * K + c0 * 8;
    uint32_t stA[4], stB[4];
#pragma unroll
    for (int i = 0; i < 4; i++) {
        uint32_t off = (uint32_t)srow * 128 +
                       (((uint32_t)((c0 + i) ^ sxor)) << 4);
        stA[i] = sb + off;
        stB[i] = sb + 16384 + off;
    }

#define LOAD_S128(s, t_)                                                   \
    do {                                                                   \
        const __half* _a = gA + (t_) * 64;                                 \
        const __half* _b = gB + (t_) * 64;                                 \
        uint32_t _so = (uint32_t)(s)*G128_STAGE;                           \
        _Pragma("unroll") for (int _i = 0; _i < 4; _i++) {                 \
            cp16(stA[_i] + _so, _a + _i * 8);                              \
            cp16(stB[_i] + _so, _b + _i * 8);                              \
        }                                                                  \
        asm volatile("cp.async.commit_group;");                            \
    } while (0)

    const int arow7 = lane & 7;
    const int a8 = ((lane >> 3) & 1) * 8;
    const int acbit = lane >> 4;
    uint32_t aBase[4];
#pragma unroll
    for (int mf = 0; mf < 4; mf++)
        aBase[mf] = sb + (uint32_t)(wm * 64 + mf * 16 + arow7 + a8) * 128;
    uint32_t aoff[4];
#pragma unroll
    for (int kc = 0; kc < 4; kc++)
        aoff[kc] = ((uint32_t)((2 * kc + acbit) ^ arow7)) << 4;

    const int brow7 = lane & 7;
    const int bn8 = (lane >> 4) * 8;
    const int bcb = (lane >> 3) & 1;
    uint32_t bBase[2];
#pragma unroll
    for (int p = 0; p < 2; p++)
        bBase[p] =
            sb + 16384 + (uint32_t)(wn * 32 + p * 16 + brow7 + bn8) * 128;
    uint32_t boff[4];
#pragma unroll
    for (int kc = 0; kc < 4; kc++)
        boff[kc] = ((uint32_t)((2 * kc + bcb) ^ brow7)) << 4;

    float acc[4][4][4];
#pragma unroll
    for (int i = 0; i < 4; i++)
#pragma unroll
        for (int j = 0; j < 4; j++)
#pragma unroll
            for (int c = 0; c < 4; c++) acc[i][j][c] = 0.f;

    const int T = K / 64;
    LOAD_S128(0, 0);
    LOAD_S128(1, 1);

    int s = 0;
    for (int t = 0; t < T; t++) {
        if (t + 1 < T)
            asm volatile("cp.async.wait_group 1;");
        else
            asm volatile("cp.async.wait_group 0;");
        __syncthreads();
        if (t + 2 < T) LOAD_S128((s + 2) % 3, t + 2);

        uint32_t so = (uint32_t)s * G128_STAGE;
#pragma unroll
        for (int kc = 0; kc < 4; kc++) {
            uint32_t af[4][4];
#pragma unroll
            for (int mf = 0; mf < 4; mf++)
                LDSM_X4(af[mf][0], af[mf][1], af[mf][2], af[mf][3],
                        aBase[mf] + so + aoff[kc]);
#pragma unroll
            for (int p = 0; p < 2; p++) {
                uint32_t bf0[2], bf1[2];
                LDSM_X4(bf0[0], bf0[1], bf1[0], bf1[1],
                        bBase[p] + so + boff[kc]);
#pragma unroll
                for (int mf = 0; mf < 4; mf++) {
                    MMA_FP16(acc[mf][2 * p], af[mf], bf0);
                    MMA_FP16(acc[mf][2 * p + 1], af[mf], bf1);
                }
            }
        }
        s = (s + 1) % 3;
    }

    int r = lane >> 2, kq = lane & 3;
#pragma unroll
    for (int mf = 0; mf < 4; mf++) {
#pragma unroll
        for (int nf = 0; nf < 4; nf++) {
            int n0 = bn + wn * 32 + nf * 8 + kq * 2;
#pragma unroll
            for (int half = 0; half < 2; half++) {
                int m0 = bm + wm * 64 + mf * 16 + r + half * 8;
                float2 v;
                v.x = acc[mf][nf][half * 2 + 0];
                v.y = acc[mf][nf][half * 2 + 1];
                if (flags & FLAG_BIAS) {
                    v.x += bias[n0];
                    v.y += bias[n0 + 1];
                }
                if (flags & FLAG_GELU) {
                    v.x = gelu_tanh(v.x);
                    v.y = gelu_tanh(v.y);
                }
                if (flags & FLAG_HALF) {
                    __half2* dst =
                        (__half2*)((__half*)Cv + (size_t)m0 * Nout + n0);
                    *dst = __floats2half2_rn(v.x, v.y);
                } else {
                    float2* dst =
                        (float2*)((float*)Cv + (size_t)m0 * Nout + n0);
                    if (flags & FLAG_ADD) {
                        float2 old = *dst;
                        v.x += old.x;
                        v.y += old.y;
                    }
                    *dst = v;
                }
            }
        }
    }
}

// ---------------- flash attention w/ tensor cores (causal + ALiBi) ----------
__global__ __launch_bounds__(128) void attn_mma(const __half* __restrict__ qkv,
                                                __half* __restrict__ out) {
    __shared__ __align__(16) char smem[40960];
    const uint32_t sb = (uint32_t)__cvta_generic_to_shared(smem);
    const int tid = threadIdx.x;
    const int w = tid >> 5, lane = tid & 31;
    const int qt = blockIdx.x, bh = blockIdx.y;
    const int b = bh / NH, h = bh % NH;
    const float slope = c_slopes[h];

    const int srow = tid >> 1, c0 = (tid & 1) * 4;
    const int sxor = srow & 7;
    const uint32_t rowoff = sb + (uint32_t)srow * 128;

    {
        const __half* gQ = qkv +
                           (size_t)(b * Nn + qt * 64 + srow) * QKVW + h * DH +
                           c0 * 8;
#pragma unroll
        for (int i = 0; i < 4; i++)
            cp16(rowoff + (((uint32_t)((c0 + i) ^ sxor)) << 4), gQ + i * 8);
        asm volatile("cp.async.commit_group;");
    }

#define LOAD_KV(kt_, buf_)                                                   \
    do {                                                                     \
        const __half* _gK = qkv +                                            \
                            (size_t)(b * Nn + (kt_)*64 + srow) * QKVW + EMB + \
                            h * DH + c0 * 8;                                 \
        uint32_t _base = rowoff + 8192 + (uint32_t)(buf_)*16384;             \
        _Pragma("unroll") for (int _i = 0; _i < 4; _i++)                     \
            cp16(_base + (((uint32_t)((c0 + _i) ^ sxor)) << 4), _gK + _i * 8); \
        _Pragma("unroll") for (int _i = 0; _i < 4; _i++)                     \
            cp16(_base + 8192 + (((uint32_t)((c0 + _i) ^ sxor)) << 4),       \
                 _gK + EMB + _i * 8);                                        \
        asm volatile("cp.async.commit_group;");                              \
    } while (0)

    LOAD_KV(0, 0);

    asm volatile("cp.async.wait_group 1;");
    __syncthreads();
    const int arow7 = lane & 7;
    const int a8 = ((lane >> 3) & 1) * 8;
    const int acbit = lane >> 4;
    uint32_t Qf[4][4];
    {
        uint32_t qrow = (uint32_t)(w * 16 + arow7 + a8);
        uint32_t qaddr = sb + qrow * 128;
#pragma unroll
        for (int kc = 0; kc < 4; kc++)
            LDSM_X4(Qf[kc][0], Qf[kc][1], Qf[kc][2], Qf[kc][3],
                    qaddr + (((uint32_t)((2 * kc + acbit) ^ arow7)) << 4));
    }

    const int r = lane >> 2, kq = lane & 3;
    const int row0 = qt * 64 + w * 16 + r;
    const int row1 = row0 + 8;
    float m0 = -1e30f, m1 = -1e30f, l0 = 0.f, l1 = 0.f;
    float O[8][4];
#pragma unroll
    for (int dt = 0; dt < 8; dt++)
#pragma unroll
        for (int c = 0; c < 4; c++) O[dt][c] = 0.f;

    const int bg = lane >> 3;
    const int bcb = bg & 1;
    const int brofs = (bg >> 1) * 8;
    const int brow7 = lane & 7;
    const uint32_t vrowlocal = (uint32_t)((lane & 7) + ((lane >> 3) & 1) * 8);
    const int vcbit = lane >> 4;

    for (int kt = 0; kt <= qt; kt++) {
        int buf = kt & 1;
        if (kt < qt) LOAD_KV(kt + 1, buf ^ 1);
        if (kt < qt)
            asm volatile("cp.async.wait_group 1;");
        else
            asm volatile("cp.async.wait_group 0;");
        __syncthreads();

        uint32_t kbase = sb + 8192 + (uint32_t)buf * 16384;
        uint32_t vbase = kbase + 8192;

        float S[8][4];
#pragma unroll
        for (int nt = 0; nt < 8; nt++)
#pragma unroll
            for (int c = 0; c < 4; c++) S[nt][c] = 0.f;
#pragma unroll
        for (int kc = 0; kc < 4; kc++) {
            uint32_t bf[8][2];
#pragma unroll
            for (int p = 0; p < 4; p++) {
                uint32_t rr = (uint32_t)(p * 16 + brofs + brow7);
                LDSM_X4(bf[2 * p][0], bf[2 * p][1], bf[2 * p + 1][0],
                        bf[2 * p + 1][1],
                        kbase + rr * 128 +
                            (((uint32_t)((2 * kc + bcb) ^ brow7)) << 4));
            }
#pragma unroll
            for (int nt = 0; nt < 8; nt++) MMA_FP16(S[nt], Qf[kc], bf[nt]);
        }

        bool diag = (kt == qt);
        float mx0 = -1e30f, mx1 = -1e30f;
#pragma unroll
        for (int nt = 0; nt < 8; nt++) {
            int colb = kt * 64 + nt * 8 + kq * 2;
#pragma unroll
            for (int c = 0; c < 4; c++) {
                int col = colb + (c & 1);
                float v = S[nt][c] * 0.125f + slope * (float)col;
                if (diag && col > ((c < 2) ? row0 : row1)) v = -1e30f;
                S[nt][c] = v;
                if (c < 2)
                    mx0 = fmaxf(mx0, v);
                else
                    mx1 = fmaxf(mx1, v);
            }
        }
        mx0 = fmaxf(mx0, __shfl_xor_sync(0xffffffffu, mx0, 1));
        mx0 = fmaxf(mx0, __shfl_xor_sync(0xffffffffu, mx0, 2));
        mx1 = fmaxf(mx1, __shfl_xor_sync(0xffffffffu, mx1, 1));
        mx1 = fmaxf(mx1, __shfl_xor_sync(0xffffffffu, mx1, 2));

        float nm0 = fmaxf(m0, mx0), nm1 = fmaxf(m1, mx1);
        float corr0 = __expf(m0 - nm0), corr1 = __expf(m1 - nm1);
        m0 = nm0;
        m1 = nm1;

        float sum0 = 0.f, sum1 = 0.f;
#pragma unroll
        for (int nt = 0; nt < 8; nt++) {
            float p0 = __expf(S[nt][0] - m0);
            float p1 = __expf(S[nt][1] - m0);
            float p2 = __expf(S[nt][2] - m1);
            float p3 = __expf(S[nt][3] - m1);
            S[nt][0] = p0;
            S[nt][1] = p1;
            S[nt][2] = p2;
            S[nt][3] = p3;
            sum0 += p0 + p1;
            sum1 += p2 + p3;
        }
        sum0 += __shfl_xor_sync(0xffffffffu, sum0, 1);
        sum0 += __shfl_xor_sync(0xffffffffu, sum0, 2);
        sum1 += __shfl_xor_sync(0xffffffffu, sum1, 1);
        sum1 += __shfl_xor_sync(0xffffffffu, sum1, 2);
        l0 = l0 * corr0 + sum0;
        l1 = l1 * corr1 + sum1;

#pragma unroll
        for (int dt = 0; dt < 8; dt++) {
            O[dt][0] *= corr0;
            O[dt][1] *= corr0;
            O[dt][2] *= corr1;
            O[dt][3] *= corr1;
        }

#pragma unroll
        for (int kc2 = 0; kc2 < 4; kc2++) {
            uint32_t aP[4];
            aP[0] = packh2(S[2 * kc2][0], S[2 * kc2][1]);
            aP[1] = packh2(S[2 * kc2][2], S[2 * kc2][3]);
            aP[2] = packh2(S[2 * kc2 + 1][0], S[2 * kc2 + 1][1]);
            aP[3] = packh2(S[2 * kc2 + 1][2], S[2 * kc2 + 1][3]);
            uint32_t vrow = (uint32_t)(kc2 * 16) + vrowlocal;
            uint32_t vra = vbase + vrow * 128;
            uint32_t vswz = vrow & 7;
#pragma unroll
            for (int cc = 0; cc < 4; cc++) {
                uint32_t v0, v1, v2, v3;
                LDSM_X4_T(v0, v1, v2, v3,
                          vra + (((uint32_t)((2 * cc + vcbit) ^ vswz)) << 4));
                uint32_t bA[2] = {v0, v1}, bB[2] = {v2, v3};
                MMA_FP16(O[2 * cc], aP, bA);
                MMA_FP16(O[2 * cc + 1], aP, bB);
            }
        }
        __syncthreads();
    }

    float i0 = 1.0f / l0, i1 = 1.0f / l1;
    __half* o0 = out + (size_t)(b * Nn + row0) * EMB + h * DH + kq * 2;
    __half* o1 = out + (size_t)(b * Nn + row1) * EMB + h * DH + kq * 2;
#pragma unroll
    for (int dt = 0; dt < 8; dt++) {
        *(__half2*)(o0 + dt * 8) =
            __floats2half2_rn(O[dt][0] * i0, O[dt][1] * i0);
        *(__half2*)(o1 + dt * 8) =
            __floats2half2_rn(O[dt][2] * i1, O[dt][3] * i1);
    }
}

// ---------------- host orchestration -----------------------------------------
extern "C" void kernel_launch(void* const* d_in, const int* in_sizes, int n_in,
                              void* d_out, int out_size) {
    const float* x = (const float*)d_in[0];
    const float* wqkv = (const float*)d_in[1];
    const float* bqkv = (const float*)d_in[2];
    const float* wo = (const float*)d_in[3];
    const float* bo = (const float*)d_in[4];
    const float* ln1s = (const float*)d_in[5];
    const float* ln1b = (const float*)d_in[6];
    const float* ln2s = (const float*)d_in[7];
    const float* ln2b = (const float*)d_in[8];
    const float* w1 = (const float*)d_in[9];
    const float* w2 = (const float*)d_in[10];
    const float* lnfs = (const float*)d_in[11];
    const float* lnfb = (const float*)d_in[12];
    float* out = (float*)d_out;

    float* p_h;
    __half *p_y, *p_qkv, *p_o, *p_mid, *p_wqkv, *p_wo, *p_w1, *p_w2;
    cudaGetSymbolAddress((void**)&p_h, g_h);
    cudaGetSymbolAddress((void**)&p_y, g_y);
    cudaGetSymbolAddress((void**)&p_qkv, g_qkv);
    cudaGetSymbolAddress((void**)&p_o, g_o);
    cudaGetSymbolAddress((void**)&p_mid, g_mid);
    cudaGetSymbolAddress((void**)&p_wqkv, g_wqkv);
    cudaGetSymbolAddress((void**)&p_wo, g_wo);
    cudaGetSymbolAddress((void**)&p_w1, g_w1);
    cudaGetSymbolAddress((void**)&p_w2, g_w2);

    cudaFuncSetAttribute(gemm64, cudaFuncAttributeMaxDynamicSharedMemorySize,
                         GEMM_SMEM_64);
    cudaFuncSetAttribute(gemm128, cudaFuncAttributeMaxDynamicSharedMemorySize,
                         GEMM_SMEM_128);

    copy_kernel<<<(TOK * EMB + 255) / 256, 256>>>(x);

    transpose_half_all<<<TALL, dim3(32, 8)>>>(wqkv, wo, w1, w2, p_wqkv, p_wo,
                                              p_w1, p_w2);

    for (int L = 0; L < DEPTH; L++) {
        ln_kernel<<<TOK, 256>>>(p_h, ln1s + L * EMB, ln1b + L * EMB, p_y, 1);
        {  // qkv = y @ Wqkv + b (fp16 out)
            dim3 grid(3 * EMB / 128, TOK / 128);
            gemm128<<<grid, 256, GEMM_SMEM_128>>>(
                p_y, p_wqkv + (size_t)L * EMB * 3 * EMB, bqkv + L * 3 * EMB,
                p_qkv, EMB, 3 * EMB, FLAG_BIAS | FLAG_HALF);
        }
        {  // flash attention
            dim3 grid(Nn / 64, Bb * NH);
            attn_mma<<<grid, 128>>>(p_qkv, p_o);
        }
        {  // h += o @ Wo + bo
            dim3 grid(EMB / 64, TOK / 128);
            gemm64<<<grid, 128, GEMM_SMEM_64>>>(
                p_o, p_wo + (size_t)L * EMB * EMB, bo + L * EMB, p_h, EMB, EMB,
                FLAG_BIAS | FLAG_ADD);
        }
        ln_kernel<<<TOK, 256>>>(p_h, ln2s + L * EMB, ln2b + L * EMB, p_y, 1);
        {  // mid = gelu(y @ W1) (half out)
            dim3 grid(FF / 128, TOK / 128);
            gemm128<<<grid, 256, GEMM_SMEM_128>>>(
                p_y, p_w1 + (size_t)L * EMB * FF, nullptr, p_mid, EMB, FF,
                FLAG_GELU | FLAG_HALF);
        }
        {  // h += mid @ W2
            dim3 grid(EMB / 64, TOK / 128);
            gemm64<<<grid, 128, GEMM_SMEM_64>>>(
                p_mid, p_w2 + (size_t)L * FF * EMB, nullptr, p_h, FF, EMB,
                FLAG_ADD);
        }
    }

    ln_kernel<<<TOK, 256>>>(p_h, lnfs, lnfb, out, 0);
}

// round 14
// speedup vs baseline: 1.0382x; 1.0382x over previous
#include <cuda_runtime.h>
#include <cuda_fp16.h>
#include <math.h>
#include <stdint.h>

#define Bb 2
#define Nn 2048
#define EMB 768
#define NH 12
#define DH 64
#define DEPTH 6
#define FF 3072
#define TOK (Bb * Nn)  // 4096
#define QKVW (3 * EMB) // 2304
#define LN_EPS 1e-6f

// ---------------- scratch (static device globals) ---------------------------
__device__ float g_h[TOK * EMB];
__device__ __half g_y[TOK * EMB];
__device__ __half g_qkv[TOK * 3 * EMB];
__device__ __half g_o[TOK * EMB];
__device__ __half g_mid[TOK * FF];
__device__ float g_part[3 * TOK * EMB];  // split-K partials for w2
__device__ __half g_wqkv[DEPTH * EMB * 3 * EMB];
__device__ __half g_wo[DEPTH * EMB * EMB];
__device__ __half g_w1[DEPTH * EMB * FF];
__device__ __half g_w2[DEPTH * FF * EMB];

__constant__ float c_slopes[NH] = {
    0.5f, 0.25f, 0.125f, 0.0625f, 0.03125f, 0.015625f, 0.0078125f, 0.00390625f,
    0.70710678118654752f, 0.35355339059327376f, 0.17677669529663688f,
    0.08838834764831844f};

__device__ __forceinline__ void cp16(uint32_t dst, const void* src) {
    asm volatile("cp.async.cg.shared.global [%0], [%1], 16;" ::"r"(dst),
                 "l"(src));
}

__device__ __forceinline__ uint32_t packh2(float a, float b) {
    __half2 h = __floats2half2_rn(a, b);
    return *(uint32_t*)&h;
}

#define MMA_FP16(d, a, b)                                                     \
    asm volatile(                                                             \
        "mma.sync.aligned.m16n8k16.row.col.f32.f16.f16.f32 "                  \
        "{%0,%1,%2,%3},{%4,%5,%6,%7},{%8,%9},{%0,%1,%2,%3};"                  \
        : "+f"(d[0]), "+f"(d[1]), "+f"(d[2]), "+f"(d[3])                      \
        : "r"(a[0]), "r"(a[1]), "r"(a[2]), "r"(a[3]), "r"(b[0]), "r"(b[1]))

#define LDSM_X4(r0, r1, r2, r3, addr)                                        \
    asm volatile(                                                            \
        "ldmatrix.sync.aligned.m8n8.x4.shared.b16 {%0,%1,%2,%3}, [%4];"      \
        : "=r"(r0), "=r"(r1), "=r"(r2), "=r"(r3)                             \
        : "r"(addr))

#define LDSM_X4_T(r0, r1, r2, r3, addr)                                      \
    asm volatile(                                                            \
        "ldmatrix.sync.aligned.m8n8.x4.trans.shared.b16 {%0,%1,%2,%3}, "     \
        "[%4];"                                                              \
        : "=r"(r0), "=r"(r1), "=r"(r2), "=r"(r3)                             \
        : "r"(addr))

// ---------------- copy x -> h ------------------------------------------------
__global__ void copy_kernel(const float* __restrict__ x) {
    int i = blockIdx.x * blockDim.x + threadIdx.x;
    if (i < TOK * EMB) g_h[i] = x[i];
}

// ---------------- fused transpose + fp16 convert of ALL weights -------------
#define TQKV (72 * 24 * DEPTH)
#define TWO (24 * 24 * DEPTH)
#define TW1 (96 * 24 * DEPTH)
#define TW2 (24 * 96 * DEPTH)
#define TALL (TQKV + TWO + TW1 + TW2)

__global__ void transpose_half_all(const float* __restrict__ wqkv,
                                   const float* __restrict__ wo,
                                   const float* __restrict__ w1,
                                   const float* __restrict__ w2,
                                   __half* __restrict__ pwqkv,
                                   __half* __restrict__ pwo,
                                   __half* __restrict__ pw1,
                                   __half* __restrict__ pw2) {
    __shared__ float tile[32][33];
    int b = blockIdx.x;
    const float* W;
    __half* Wt;
    int K, N;
    if (b < TQKV) {
        W = wqkv; Wt = pwqkv; K = EMB; N = 3 * EMB;
    } else if (b < TQKV + TWO) {
        b -= TQKV; W = wo; Wt = pwo; K = EMB; N = EMB;
    } else if (b < TQKV + TWO + TW1) {
        b -= TQKV + TWO; W = w1; Wt = pw1; K = EMB; N = FF;
    } else {
        b -= TQKV + TWO + TW1; W = w2; Wt = pw2; K = FF; N = EMB;
    }
    int ntiles = N / 32, tpl = ntiles * (K / 32);
    int layer = b / tpl, rem = b % tpl;
    int bn = (rem % ntiles) * 32, bk = (rem / ntiles) * 32;
    W += (size_t)layer * K * N;
    Wt += (size_t)layer * K * N;
    int tx = threadIdx.x, ty = threadIdx.y;
#pragma unroll
    for (int i = 0; i < 32; i += 8)
        tile[ty + i][tx] = W[(size_t)(bk + ty + i) * N + bn + tx];
    __syncthreads();
#pragma unroll
    for (int i = 0; i < 32; i += 8)
        Wt[(size_t)(bn + ty + i) * K + bk + tx] =
            __float2half_rn(tile[tx][ty + i]);
}

// ---------------- LayerNorm (plain) ------------------------------------------
__global__ void ln_kernel(const float* __restrict__ in,
                          const float* __restrict__ scale,
                          const float* __restrict__ bias, void* __restrict__ o,
                          int half_out) {
    int row = blockIdx.x;
    const float* p = in + (size_t)row * EMB;
    float s = 0.f, ss = 0.f;
    for (int i = threadIdx.x; i < EMB; i += 256) {
        float v = p[i];
        s += v;
        ss += v * v;
    }
#pragma unroll
    for (int of = 16; of; of >>= 1) {
        s += __shfl_xor_sync(0xffffffffu, s, of);
        ss += __shfl_xor_sync(0xffffffffu, ss, of);
    }
    __shared__ float sh_s[8], sh_ss[8];
    int w = threadIdx.x >> 5, lane = threadIdx.x & 31;
    if (lane == 0) { sh_s[w] = s; sh_ss[w] = ss; }
    __syncthreads();
    if (threadIdx.x < 32) {
        s = (lane < 8) ? sh_s[lane] : 0.f;
        ss = (lane < 8) ? sh_ss[lane] : 0.f;
#pragma unroll
        for (int of = 4; of; of >>= 1) {
            s += __shfl_xor_sync(0xffffffffu, s, of);
            ss += __shfl_xor_sync(0xffffffffu, ss, of);
        }
        if (lane == 0) { sh_s[0] = s; sh_ss[0] = ss; }
    }
    __syncthreads();
    float mean = sh_s[0] * (1.0f / EMB);
    float var = sh_ss[0] * (1.0f / EMB) - mean * mean;
    float inv = rsqrtf(var + LN_EPS);
    if (half_out) {
        __half* q = (__half*)o + (size_t)row * EMB;
        for (int i = threadIdx.x; i < EMB; i += 256)
            q[i] = __float2half_rn((p[i] - mean) * inv * scale[i] + bias[i]);
    } else {
        float* q = (float*)o + (size_t)row * EMB;
        for (int i = threadIdx.x; i < EMB; i += 256)
            q[i] = (p[i] - mean) * inv * scale[i] + bias[i];
    }
}

// ---------------- LayerNorm fused with split-K partial reduction ------------
// h[row] += p0+p1+p2 (written back), then LN(h) -> o (half or float)
__global__ void ln_fused(float* __restrict__ h, const float* __restrict__ P,
                         const float* __restrict__ scale,
                         const float* __restrict__ bias, void* __restrict__ o,
                         int half_out) {
    int row = blockIdx.x;
    float* hp = h + (size_t)row * EMB;
    const float* p0 = P + (size_t)row * EMB;
    const float* p1 = p0 + (size_t)TOK * EMB;
    const float* p2 = p1 + (size_t)TOK * EMB;
    __shared__ float buf[EMB];
    float s = 0.f, ss = 0.f;
    for (int i = threadIdx.x; i < EMB; i += 256) {
        float v = hp[i] + p0[i] + p1[i] + p2[i];
        hp[i] = v;
        buf[i] = v;
        s += v;
        ss += v * v;
    }
#pragma unroll
    for (int of = 16; of; of >>= 1) {
        s += __shfl_xor_sync(0xffffffffu, s, of);
        ss += __shfl_xor_sync(0xffffffffu, ss, of);
    }
    __shared__ float sh_s[8], sh_ss[8];
    int w = threadIdx.x >> 5, lane = threadIdx.x & 31;
    if (lane == 0) { sh_s[w] = s; sh_ss[w] = ss; }
    __syncthreads();
    if (threadIdx.x < 32) {
        s = (lane < 8) ? sh_s[lane] : 0.f;
        ss = (lane < 8) ? sh_ss[lane] : 0.f;
#pragma unroll
        for (int of = 4; of; of >>= 1) {
            s += __shfl_xor_sync(0xffffffffu, s, of);
            ss += __shfl_xor_sync(0xffffffffu, ss, of);
        }
        if (lane == 0) { sh_s[0] = s; sh_ss[0] = ss; }
    }
    __syncthreads();
    float mean = sh_s[0] * (1.0f / EMB);
    float var = sh_ss[0] * (1.0f / EMB) - mean * mean;
    float inv = rsqrtf(var + LN_EPS);
    if (half_out) {
        __half* q = (__half*)o + (size_t)row * EMB;
        for (int i = threadIdx.x; i < EMB; i += 256)
            q[i] = __float2half_rn((buf[i] - mean) * inv * scale[i] + bias[i]);
    } else {
        float* q = (float*)o + (size_t)row * EMB;
        for (int i = threadIdx.x; i < EMB; i += 256)
            q[i] = (buf[i] - mean) * inv * scale[i] + bias[i];
    }
}

#define FLAG_BIAS 1
#define FLAG_GELU 2
#define FLAG_ADD 4
#define FLAG_HALF 8

#define STAGES 4
#define A_STAGE 8192

__device__ __forceinline__ float gelu_tanh(float x) {
    const float k0 = 0.7978845608028654f;
    return 0.5f * x * (1.0f + tanhf(k0 * (x + 0.044715f * x * x * x)));
}

// ---------------- fp16 GEMM, CTA 128x64, 128 thr, KT=32, 4 CTA/SM -----------
#define G64_STAGE (A_STAGE + 4096)
#define GEMM_SMEM_64 (STAGES * G64_STAGE)

__global__ __launch_bounds__(128, 4) void gemm64(
    const __half* __restrict__ A, const __half* __restrict__ Wt,
    const float* __restrict__ bias, void* __restrict__ Cv, int K, int Nout,
    int flags) {
    extern __shared__ char smem[];
    const uint32_t sb = (uint32_t)__cvta_generic_to_shared(smem);
    const int tid = threadIdx.x;
    const int warp = tid >> 5, lane = tid & 31;
    const int wm = warp >> 1, wn = warp & 1;
    const int bm = blockIdx.y * 128, bn = blockIdx.x * 64;

    const __half* gA = A + (size_t)(bm + tid) * K;
    uint32_t stA[4];
#pragma unroll
    for (int c = 0; c < 4; c++)
        stA[c] = sb + (uint32_t)tid * 64 +
                 (((uint32_t)(c ^ ((tid >> 1) & 3))) << 4);
    const int brow = tid >> 1, bc0 = (tid & 1) * 2;
    const __half* gB = Wt + (size_t)(bn + brow) * K + bc0 * 8;
    uint32_t stB[2];
#pragma unroll
    for (int i = 0; i < 2; i++)
        stB[i] = sb + A_STAGE + (uint32_t)brow * 64 +
                 (((uint32_t)((bc0 + i) ^ ((brow >> 1) & 3))) << 4);

#define LOAD_S64(s, t_)                                                    \
    do {                                                                   \
        const __half* _a = gA + (t_) * 32;                                 \
        const __half* _b = gB + (t_) * 32;                                 \
        uint32_t _so = (uint32_t)(s)*G64_STAGE;                            \
        _Pragma("unroll") for (int _c = 0; _c < 4; _c++)                   \
            cp16(stA[_c] + _so, _a + _c * 8);                              \
        _Pragma("unroll") for (int _i = 0; _i < 2; _i++)                   \
            cp16(stB[_i] + _so, _b + _i * 8);                              \
        asm volatile("cp.async.commit_group;");                            \
    } while (0)

    int arow7 = lane & 7;
    int a8 = ((lane >> 3) & 1) * 8;
    int acbit = lane >> 4;
    int axor = (arow7 >> 1) & 3;
    uint32_t aBase[4];
#pragma unroll
    for (int mf = 0; mf < 4; mf++)
        aBase[mf] = sb + (uint32_t)(wm * 64 + mf * 16 + arow7 + a8) * 64;
    uint32_t aoff[2];
#pragma unroll
    for (int ks = 0; ks < 2; ks++)
        aoff[ks] = ((uint32_t)((2 * ks + acbit) ^ axor)) << 4;

    int brow7 = lane & 7;
    int bn8 = (lane >> 4) * 8;
    int bcb = (lane >> 3) & 1;
    int bxor = (brow7 >> 1) & 3;
    uint32_t bBase[2];
#pragma unroll
    for (int p = 0; p < 2; p++)
        bBase[p] =
            sb + A_STAGE + (uint32_t)(wn * 32 + p * 16 + brow7 + bn8) * 64;
    uint32_t boff[2];
#pragma unroll
    for (int ks = 0; ks < 2; ks++)
        boff[ks] = ((uint32_t)((2 * ks + bcb) ^ bxor)) << 4;

    float acc[4][4][4];
#pragma unroll
    for (int i = 0; i < 4; i++)
#pragma unroll
        for (int j = 0; j < 4; j++)
#pragma unroll
            for (int c = 0; c < 4; c++) acc[i][j][c] = 0.f;

    const int T = K / 32;
    LOAD_S64(0, 0);
    LOAD_S64(1, 1);
    LOAD_S64(2, 2);

    for (int t = 0; t < T; t++) {
        int rem = ((t + 2 < T) ? (t + 2) : (T - 1)) - t;
        if (rem == 2)
            asm volatile("cp.async.wait_group 2;");
        else if (rem == 1)
            asm volatile("cp.async.wait_group 1;");
        else
            asm volatile("cp.async.wait_group 0;");
        __syncthreads();
        if (t + 3 < T) LOAD_S64((t + 3) & 3, t + 3);

        uint32_t so = (uint32_t)(t & 3) * G64_STAGE;
#pragma unroll
        for (int ks = 0; ks < 2; ks++) {
            uint32_t af[4][4];
#pragma unroll
            for (int mf = 0; mf < 4; mf++)
                LDSM_X4(af[mf][0], af[mf][1], af[mf][2], af[mf][3],
                        aBase[mf] + so + aoff[ks]);
#pragma unroll
            for (int p = 0; p < 2; p++) {
                uint32_t bf0[2], bf1[2];
                LDSM_X4(bf0[0], bf0[1], bf1[0], bf1[1],
                        bBase[p] + so + boff[ks]);
#pragma unroll
                for (int mf = 0; mf < 4; mf++) {
                    MMA_FP16(acc[mf][2 * p], af[mf], bf0);
                    MMA_FP16(acc[mf][2 * p + 1], af[mf], bf1);
                }
            }
        }
    }

    int r = lane >> 2, kq = lane & 3;
#pragma unroll
    for (int mf = 0; mf < 4; mf++) {
#pragma unroll
        for (int nf = 0; nf < 4; nf++) {
            int n0 = bn + wn * 32 + nf * 8 + kq * 2;
#pragma unroll
            for (int half = 0; half < 2; half++) {
                int m0 = bm + wm * 64 + mf * 16 + r + half * 8;
                float2 v;
                v.x = acc[mf][nf][half * 2 + 0];
                v.y = acc[mf][nf][half * 2 + 1];
                if (flags & FLAG_BIAS) {
                    v.x += bias[n0];
                    v.y += bias[n0 + 1];
                }
                if (flags & FLAG_GELU) {
                    v.x = gelu_tanh(v.x);
                    v.y = gelu_tanh(v.y);
                }
                if (flags & FLAG_HALF) {
                    __half2* dst =
                        (__half2*)((__half*)Cv + (size_t)m0 * Nout + n0);
                    *dst = __floats2half2_rn(v.x, v.y);
                } else {
                    float2* dst =
                        (float2*)((float*)Cv + (size_t)m0 * Nout + n0);
                    if (flags & FLAG_ADD) {
                        float2 old = *dst;
                        v.x += old.x;
                        v.y += old.y;
                    }
                    *dst = v;
                }
            }
        }
    }
}

// ---------------- split-K gemm: CTA 128x64, z = k-slice, fp32 partial out ---
__global__ __launch_bounds__(128, 4) void gemm64_sk(
    const __half* __restrict__ A, const __half* __restrict__ Wt,
    float* __restrict__ P, int K, int Ksl, int Nout) {
    extern __shared__ char smem[];
    const uint32_t sb = (uint32_t)__cvta_generic_to_shared(smem);
    const int tid = threadIdx.x;
    const int warp = tid >> 5, lane = tid & 31;
    const int wm = warp >> 1, wn = warp & 1;
    const int bm = blockIdx.y * 128, bn = blockIdx.x * 64;
    const int k0 = blockIdx.z * Ksl;
    float* Pz = P + (size_t)blockIdx.z * TOK * EMB;

    const __half* gA = A + (size_t)(bm + tid) * K + k0;
    uint32_t stA[4];
#pragma unroll
    for (int c = 0; c < 4; c++)
        stA[c] = sb + (uint32_t)tid * 64 +
                 (((uint32_t)(c ^ ((tid >> 1) & 3))) << 4);
    const int brow = tid >> 1, bc0 = (tid & 1) * 2;
    const __half* gB = Wt + (size_t)(bn + brow) * K + k0 + bc0 * 8;
    uint32_t stB[2];
#pragma unroll
    for (int i = 0; i < 2; i++)
        stB[i] = sb + A_STAGE + (uint32_t)brow * 64 +
                 (((uint32_t)((bc0 + i) ^ ((brow >> 1) & 3))) << 4);

    int arow7 = lane & 7;
    int a8 = ((lane >> 3) & 1) * 8;
    int acbit = lane >> 4;
    int axor = (arow7 >> 1) & 3;
    uint32_t aBase[4];
#pragma unroll
    for (int mf = 0; mf < 4; mf++)
        aBase[mf] = sb + (uint32_t)(wm * 64 + mf * 16 + arow7 + a8) * 64;
    uint32_t aoff[2];
#pragma unroll
    for (int ks = 0; ks < 2; ks++)
        aoff[ks] = ((uint32_t)((2 * ks + acbit) ^ axor)) << 4;

    int brow7 = lane & 7;
    int bn8 = (lane >> 4) * 8;
    int bcb = (lane >> 3) & 1;
    int bxor = (brow7 >> 1) & 3;
    uint32_t bBase[2];
#pragma unroll
    for (int p = 0; p < 2; p++)
        bBase[p] =
            sb + A_STAGE + (uint32_t)(wn * 32 + p * 16 + brow7 + bn8) * 64;
    uint32_t boff[2];
#pragma unroll
    for (int ks = 0; ks < 2; ks++)
        boff[ks] = ((uint32_t)((2 * ks + bcb) ^ bxor)) << 4;

    float acc[4][4][4];
#pragma unroll
    for (int i = 0; i < 4; i++)
#pragma unroll
        for (int j = 0; j < 4; j++)
#pragma unroll
            for (int c = 0; c < 4; c++) acc[i][j][c] = 0.f;

    const int T = Ksl / 32;
    LOAD_S64(0, 0);
    LOAD_S64(1, 1);
    LOAD_S64(2, 2);

    for (int t = 0; t < T; t++) {
        int rem = ((t + 2 < T) ? (t + 2) : (T - 1)) - t;
        if (rem == 2)
            asm volatile("cp.async.wait_group 2;");
        else if (rem == 1)
            asm volatile("cp.async.wait_group 1;");
        else
            asm volatile("cp.async.wait_group 0;");
        __syncthreads();
        if (t + 3 < T) LOAD_S64((t + 3) & 3, t + 3);

        uint32_t so = (uint32_t)(t & 3) * G64_STAGE;
#pragma unroll
        for (int ks = 0; ks < 2; ks++) {
            uint32_t af[4][4];
#pragma unroll
            for (int mf = 0; mf < 4; mf++)
                LDSM_X4(af[mf][0], af[mf][1], af[mf][2], af[mf][3],
                        aBase[mf] + so + aoff[ks]);
#pragma unroll
            for (int p = 0; p < 2; p++) {
                uint32_t bf0[2], bf1[2];
                LDSM_X4(bf0[0], bf0[1], bf1[0], bf1[1],
                        bBase[p] + so + boff[ks]);
#pragma unroll
                for (int mf = 0; mf < 4; mf++) {
                    MMA_FP16(acc[mf][2 * p], af[mf], bf0);
                    MMA_FP16(acc[mf][2 * p + 1], af[mf], bf1);
                }
            }
        }
    }

    int r = lane >> 2, kq = lane & 3;
#pragma unroll
    for (int mf = 0; mf < 4; mf++) {
#pragma unroll
        for (int nf = 0; nf < 4; nf++) {
            int n0 = bn + wn * 32 + nf * 8 + kq * 2;
#pragma unroll
            for (int half = 0; half < 2; half++) {
                int m0 = bm + wm * 64 + mf * 16 + r + half * 8;
                float2 v;
                v.x = acc[mf][nf][half * 2 + 0];
                v.y = acc[mf][nf][half * 2 + 1];
                *(float2*)&Pz[(size_t)m0 * Nout + n0] = v;
            }
        }
    }
}

// ---------------- fp16 GEMM, CTA 128x128, 256 thr, KT=32, 2 CTA/SM ----------
#define G128_STAGE (A_STAGE + 8192)
#define GEMM_SMEM_128 (STAGES * G128_STAGE)

__global__ __launch_bounds__(256, 2) void gemm128(
    const __half* __restrict__ A, const __half* __restrict__ Wt,
    const float* __restrict__ bias, void* __restrict__ Cv, int K, int Nout,
    int flags) {
    extern __shared__ char smem[];
    const uint32_t sb = (uint32_t)__cvta_generic_to_shared(smem);
    const int tid = threadIdx.x;
    const int warp = tid >> 5, lane = tid & 31;
    const int wm = warp >> 2, wn = warp & 3;
    const int bm = blockIdx.y * 128, bn = blockIdx.x * 128;

    const int srow = tid >> 1, sc0 = (tid & 1) * 2;
    const __half* gA = A + (size_t)(bm + srow) * K + sc0 * 8;
    const __half* gB = Wt + (size_t)(bn + srow) * K + sc0 * 8;
    uint32_t stA[2], stB[2];
#pragma unroll
    for (int i = 0; i < 2; i++) {
        uint32_t off = (uint32_t)srow * 64 +
                       (((uint32_t)((sc0 + i) ^ ((srow >> 1) & 3))) << 4);
        stA[i] = sb + off;
        stB[i] = sb + A_STAGE + off;
    }

#define LOAD_S128(s, t_)                                                   \
    do {                                                                   \
        const __half* _a = gA + (t_) * 32;                                 \
        const __half* _b = gB + (t_) * 32;                                 \
        uint32_t _so = (uint32_t)(s)*G128_STAGE;                           \
        _Pragma("unroll") for (int _i = 0; _i < 2; _i++) {                 \
            cp16(stA[_i] + _so, _a + _i * 8);                              \
            cp16(stB[_i] + _so, _b + _i * 8);                              \
        }                                                                  \
        asm volatile("cp.async.commit_group;");                            \
    } while (0)

    int arow7 = lane & 7;
    int a8 = ((lane >> 3) & 1) * 8;
    int acbit = lane >> 4;
    int axor = (arow7 >> 1) & 3;
    uint32_t aBase[4];
#pragma unroll
    for (int mf = 0; mf < 4; mf++)
        aBase[mf] = sb + (uint32_t)(wm * 64 + mf * 16 + arow7 + a8) * 64;
    uint32_t aoff[2];
#pragma unroll
    for (int ks = 0; ks < 2; ks++)
        aoff[ks] = ((uint32_t)((2 * ks + acbit) ^ axor)) << 4;

    int brow7 = lane & 7;
    int bn8 = (lane >> 4) * 8;
    int bcb = (lane >> 3) & 1;
    int bxor = (brow7 >> 1) & 3;
    uint32_t bBase[2];
#pragma unroll
    for (int p = 0; p < 2; p++)
        bBase[p] =
            sb + A_STAGE + (uint32_t)(wn * 32 + p * 16 + brow7 + bn8) * 64;
    uint32_t boff[2];
#pragma unroll
    for (int ks = 0; ks < 2; ks++)
        boff[ks] = ((uint32_t)((2 * ks + bcb) ^ bxor)) << 4;

    float acc[4][4][4];
#pragma unroll
    for (int i = 0; i < 4; i++)
#pragma unroll
        for (int j = 0; j < 4; j++)
#pragma unroll
            for (int c = 0; c < 4; c++) acc[i][j][c] = 0.f;

    const int T = K / 32;
    LOAD_S128(0, 0);
    LOAD_S128(1, 1);
    LOAD_S128(2, 2);

    for (int t = 0; t < T; t++) {
        int rem = ((t + 2 < T) ? (t + 2) : (T - 1)) - t;
        if (rem == 2)
            asm volatile("cp.async.wait_group 2;");
        else if (rem == 1)
            asm volatile("cp.async.wait_group 1;");
        else
            asm volatile("cp.async.wait_group 0;");
        __syncthreads();
        if (t + 3 < T) LOAD_S128((t + 3) & 3, t + 3);

        uint32_t so = (uint32_t)(t & 3) * G128_STAGE;
#pragma unroll
        for (int ks = 0; ks < 2; ks++) {
            uint32_t af[4][4];
#pragma unroll
            for (int mf = 0; mf < 4; mf++)
                LDSM_X4(af[mf][0], af[mf][1], af[mf][2], af[mf][3],
                        aBase[mf] + so + aoff[ks]);
#pragma unroll
            for (int p = 0; p < 2; p++) {
                uint32_t bf0[2], bf1[2];
                LDSM_X4(bf0[0], bf0[1], bf1[0], bf1[1],
                        bBase[p] + so + boff[ks]);
#pragma unroll
                for (int mf = 0; mf < 4; mf++) {
                    MMA_FP16(acc[mf][2 * p], af[mf], bf0);
                    MMA_FP16(acc[mf][2 * p + 1], af[mf], bf1);
                }
            }
        }
    }

    int r = lane >> 2, kq = lane & 3;
#pragma unroll
    for (int mf = 0; mf < 4; mf++) {
#pragma unroll
        for (int nf = 0; nf < 4; nf++) {
            int n0 = bn + wn * 32 + nf * 8 + kq * 2;
#pragma unroll
            for (int half = 0; half < 2; half++) {
                int m0 = bm + wm * 64 + mf * 16 + r + half * 8;
                float2 v;
                v.x = acc[mf][nf][half * 2 + 0];
                v.y = acc[mf][nf][half * 2 + 1];
                if (flags & FLAG_BIAS) {
                    v.x += bias[n0];
                    v.y += bias[n0 + 1];
                }
                if (flags & FLAG_GELU) {
                    v.x = gelu_tanh(v.x);
                    v.y = gelu_tanh(v.y);
                }
                if (flags & FLAG_HALF) {
                    __half2* dst =
                        (__half2*)((__half*)Cv + (size_t)m0 * Nout + n0);
                    *dst = __floats2half2_rn(v.x, v.y);
                } else {
                    float2* dst =
                        (float2*)((float*)Cv + (size_t)m0 * Nout + n0);
                    if (flags & FLAG_ADD) {
                        float2 old = *dst;
                        v.x += old.x;
                        v.y += old.y;
                    }
                    *dst = v;
                }
            }
        }
    }
}

// ---------------- flash attention w/ tensor cores (causal + ALiBi) ----------
__global__ __launch_bounds__(128) void attn_mma(const __half* __restrict__ qkv,
                                                __half* __restrict__ out) {
    __shared__ __align__(16) char smem[40960];
    const uint32_t sb = (uint32_t)__cvta_generic_to_shared(smem);
    const int tid = threadIdx.x;
    const int w = tid >> 5, lane = tid & 31;
    const int qt = blockIdx.x, bh = blockIdx.y;
    const int b = bh / NH, h = bh % NH;
    const float slope = c_slopes[h];

    const int srow = tid >> 1, c0 = (tid & 1) * 4;
    const int sxor = srow & 7;
    const uint32_t rowoff = sb + (uint32_t)srow * 128;

    {
        const __half* gQ = qkv +
                           (size_t)(b * Nn + qt * 64 + srow) * QKVW + h * DH +
                           c0 * 8;
#pragma unroll
        for (int i = 0; i < 4; i++)
            cp16(rowoff + (((uint32_t)((c0 + i) ^ sxor)) << 4), gQ + i * 8);
        asm volatile("cp.async.commit_group;");
    }

#define LOAD_KV(kt_, buf_)                                                   \
    do {                                                                     \
        const __half* _gK = qkv +                                            \
                            (size_t)(b * Nn + (kt_)*64 + srow) * QKVW + EMB + \
                            h * DH + c0 * 8;                                 \
        uint32_t _base = rowoff + 8192 + (uint32_t)(buf_)*16384;             \
        _Pragma("unroll") for (int _i = 0; _i < 4; _i++)                     \
            cp16(_base + (((uint32_t)((c0 + _i) ^ sxor)) << 4), _gK + _i * 8); \
        _Pragma("unroll") for (int _i = 0; _i < 4; _i++)                     \
            cp16(_base + 8192 + (((uint32_t)((c0 + _i) ^ sxor)) << 4),       \
                 _gK + EMB + _i * 8);                                        \
        asm volatile("cp.async.commit_group;");                              \
    } while (0)

    LOAD_KV(0, 0);

    asm volatile("cp.async.wait_group 1;");
    __syncthreads();
    const int arow7 = lane & 7;
    const int a8 = ((lane >> 3) & 1) * 8;
    const int acbit = lane >> 4;
    uint32_t Qf[4][4];
    {
        uint32_t qrow = (uint32_t)(w * 16 + arow7 + a8);
        uint32_t qaddr = sb + qrow * 128;
#pragma unroll
        for (int kc = 0; kc < 4; kc++)
            LDSM_X4(Qf[kc][0], Qf[kc][1], Qf[kc][2], Qf[kc][3],
                    qaddr + (((uint32_t)((2 * kc + acbit) ^ arow7)) << 4));
    }

    const int r = lane >> 2, kq = lane & 3;
    const int row0 = qt * 64 + w * 16 + r;
    const int row1 = row0 + 8;
    float m0 = -1e30f, m1 = -1e30f, l0 = 0.f, l1 = 0.f;
    float O[8][4];
#pragma unroll
    for (int dt = 0; dt < 8; dt++)
#pragma unroll
        for (int c = 0; c < 4; c++) O[dt][c] = 0.f;

    const int bg = lane >> 3;
    const int bcb = bg & 1;
    const int brofs = (bg >> 1) * 8;
    const int brow7 = lane & 7;
    const uint32_t vrowlocal = (uint32_t)((lane & 7) + ((lane >> 3) & 1) * 8);
    const int vcbit = lane >> 4;

    for (int kt = 0; kt <= qt; kt++) {
        int buf = kt & 1;
        if (kt < qt) LOAD_KV(kt + 1, buf ^ 1);
        if (kt < qt)
            asm volatile("cp.async.wait_group 1;");
        else
            asm volatile("cp.async.wait_group 0;");
        __syncthreads();

        uint32_t kbase = sb + 8192 + (uint32_t)buf * 16384;
        uint32_t vbase = kbase + 8192;

        float S[8][4];
#pragma unroll
        for (int nt = 0; nt < 8; nt++)
#pragma unroll
            for (int c = 0; c < 4; c++) S[nt][c] = 0.f;
#pragma unroll
        for (int kc = 0; kc < 4; kc++) {
            uint32_t bf[8][2];
#pragma unroll
            for (int p = 0; p < 4; p++) {
                uint32_t rr = (uint32_t)(p * 16 + brofs + brow7);
                LDSM_X4(bf[2 * p][0], bf[2 * p][1], bf[2 * p + 1][0],
                        bf[2 * p + 1][1],
                        kbase + rr * 128 +
                            (((uint32_t)((2 * kc + bcb) ^ brow7)) << 4));
            }
#pragma unroll
            for (int nt = 0; nt < 8; nt++) MMA_FP16(S[nt], Qf[kc], bf[nt]);
        }

        bool diag = (kt == qt);
        float mx0 = -1e30f, mx1 = -1e30f;
#pragma unroll
        for (int nt = 0; nt < 8; nt++) {
            int colb = kt * 64 + nt * 8 + kq * 2;
#pragma unroll
            for (int c = 0; c < 4; c++) {
                int col = colb + (c & 1);
                float v = S[nt][c] * 0.125f + slope * (float)col;
                if (diag && col > ((c < 2) ? row0 : row1)) v = -1e30f;
                S[nt][c] = v;
                if (c < 2)
                    mx0 = fmaxf(mx0, v);
                else
                    mx1 = fmaxf(mx1, v);
            }
        }
        mx0 = fmaxf(mx0, __shfl_xor_sync(0xffffffffu, mx0, 1));
        mx0 = fmaxf(mx0, __shfl_xor_sync(0xffffffffu, mx0, 2));
        mx1 = fmaxf(mx1, __shfl_xor_sync(0xffffffffu, mx1, 1));
        mx1 = fmaxf(mx1, __shfl_xor_sync(0xffffffffu, mx1, 2));

        float nm0 = fmaxf(m0, mx0), nm1 = fmaxf(m1, mx1);
        float corr0 = __expf(m0 - nm0), corr1 = __expf(m1 - nm1);
        m0 = nm0;
        m1 = nm1;

        float sum0 = 0.f, sum1 = 0.f;
#pragma unroll
        for (int nt = 0; nt < 8; nt++) {
            float p0 = __expf(S[nt][0] - m0);
            float p1 = __expf(S[nt][1] - m0);
            float p2 = __expf(S[nt][2] - m1);
            float p3 = __expf(S[nt][3] - m1);
            S[nt][0] = p0;
            S[nt][1] = p1;
            S[nt][2] = p2;
            S[nt][3] = p3;
            sum0 += p0 + p1;
            sum1 += p2 + p3;
        }
        sum0 += __shfl_xor_sync(0xffffffffu, sum0, 1);
        sum0 += __shfl_xor_sync(0xffffffffu, sum0, 2);
        sum1 += __shfl_xor_sync(0xffffffffu, sum1, 1);
        sum1 += __shfl_xor_sync(0xffffffffu, sum1, 2);
        l0 = l0 * corr0 + sum0;
        l1 = l1 * corr1 + sum1;

#pragma unroll
        for (int dt = 0; dt < 8; dt++) {
            O[dt][0] *= corr0;
            O[dt][1] *= corr0;
            O[dt][2] *= corr1;
            O[dt][3] *= corr1;
        }

#pragma unroll
        for (int kc2 = 0; kc2 < 4; kc2++) {
            uint32_t aP[4];
            aP[0] = packh2(S[2 * kc2][0], S[2 * kc2][1]);
            aP[1] = packh2(S[2 * kc2][2], S[2 * kc2][3]);
            aP[2] = packh2(S[2 * kc2 + 1][0], S[2 * kc2 + 1][1]);
            aP[3] = packh2(S[2 * kc2 + 1][2], S[2 * kc2 + 1][3]);
            uint32_t vrow = (uint32_t)(kc2 * 16) + vrowlocal;
            uint32_t vra = vbase + vrow * 128;
            uint32_t vswz = vrow & 7;
#pragma unroll
            for (int cc = 0; cc < 4; cc++) {
                uint32_t v0, v1, v2, v3;
                LDSM_X4_T(v0, v1, v2, v3,
                          vra + (((uint32_t)((2 * cc + vcbit) ^ vswz)) << 4));
                uint32_t bA[2] = {v0, v1}, bB[2] = {v2, v3};
                MMA_FP16(O[2 * cc], aP, bA);
                MMA_FP16(O[2 * cc + 1], aP, bB);
            }
        }
        __syncthreads();
    }

    float i0 = 1.0f / l0, i1 = 1.0f / l1;
    __half* o0 = out + (size_t)(b * Nn + row0) * EMB + h * DH + kq * 2;
    __half* o1 = out + (size_t)(b * Nn + row1) * EMB + h * DH + kq * 2;
#pragma unroll
    for (int dt = 0; dt < 8; dt++) {
        *(__half2*)(o0 + dt * 8) =
            __floats2half2_rn(O[dt][0] * i0, O[dt][1] * i0);
        *(__half2*)(o1 + dt * 8) =
            __floats2half2_rn(O[dt][2] * i1, O[dt][3] * i1);
    }
}

// ---------------- host orchestration -----------------------------------------
extern "C" void kernel_launch(void* const* d_in, const int* in_sizes, int n_in,
                              void* d_out, int out_size) {
    const float* x = (const float*)d_in[0];
    const float* wqkv = (const float*)d_in[1];
    const float* bqkv = (const float*)d_in[2];
    const float* wo = (const float*)d_in[3];
    const float* bo = (const float*)d_in[4];
    const float* ln1s = (const float*)d_in[5];
    const float* ln1b = (const float*)d_in[6];
    const float* ln2s = (const float*)d_in[7];
    const float* ln2b = (const float*)d_in[8];
    const float* w1 = (const float*)d_in[9];
    const float* w2 = (const float*)d_in[10];
    const float* lnfs = (const float*)d_in[11];
    const float* lnfb = (const float*)d_in[12];
    float* out = (float*)d_out;

    float *p_h, *p_part;
    __half *p_y, *p_qkv, *p_o, *p_mid, *p_wqkv, *p_wo, *p_w1, *p_w2;
    cudaGetSymbolAddress((void**)&p_h, g_h);
    cudaGetSymbolAddress((void**)&p_part, g_part);
    cudaGetSymbolAddress((void**)&p_y, g_y);
    cudaGetSymbolAddress((void**)&p_qkv, g_qkv);
    cudaGetSymbolAddress((void**)&p_o, g_o);
    cudaGetSymbolAddress((void**)&p_mid, g_mid);
    cudaGetSymbolAddress((void**)&p_wqkv, g_wqkv);
    cudaGetSymbolAddress((void**)&p_wo, g_wo);
    cudaGetSymbolAddress((void**)&p_w1, g_w1);
    cudaGetSymbolAddress((void**)&p_w2, g_w2);

    cudaFuncSetAttribute(gemm64, cudaFuncAttributeMaxDynamicSharedMemorySize,
                         GEMM_SMEM_64);
    cudaFuncSetAttribute(gemm64_sk, cudaFuncAttributeMaxDynamicSharedMemorySize,
                         GEMM_SMEM_64);
    cudaFuncSetAttribute(gemm128, cudaFuncAttributeMaxDynamicSharedMemorySize,
                         GEMM_SMEM_128);

    copy_kernel<<<(TOK * EMB + 255) / 256, 256>>>(x);

    transpose_half_all<<<TALL, dim3(32, 8)>>>(wqkv, wo, w1, w2, p_wqkv, p_wo,
                                              p_w1, p_w2);

    for (int L = 0; L < DEPTH; L++) {
        // ln1: plain for layer 0; fused partial-reduce + LN afterwards
        if (L == 0)
            ln_kernel<<<TOK, 256>>>(p_h, ln1s, ln1b, p_y, 1);
        else
            ln_fused<<<TOK, 256>>>(p_h, p_part, ln1s + L * EMB, ln1b + L * EMB,
                                   p_y, 1);
        {  // qkv = y @ Wqkv + b (fp16 out)
            dim3 grid(3 * EMB / 128, TOK / 128);
            gemm128<<<grid, 256, GEMM_SMEM_128>>>(
                p_y, p_wqkv + (size_t)L * EMB * 3 * EMB, bqkv + L * 3 * EMB,
                p_qkv, EMB, 3 * EMB, FLAG_BIAS | FLAG_HALF);
        }
        {  // flash attention
            dim3 grid(Nn / 64, Bb * NH);
            attn_mma<<<grid, 128>>>(p_qkv, p_o);
        }
        {  // h += o @ Wo + bo
            dim3 grid(EMB / 64, TOK / 128);
            gemm64<<<grid, 128, GEMM_SMEM_64>>>(
                p_o, p_wo + (size_t)L * EMB * EMB, bo + L * EMB, p_h, EMB, EMB,
                FLAG_BIAS | FLAG_ADD);
        }
        ln_kernel<<<TOK, 256>>>(p_h, ln2s + L * EMB, ln2b + L * EMB, p_y, 1);
        {  // mid = gelu(y @ W1) (half out)
            dim3 grid(FF / 128, TOK / 128);
            gemm128<<<grid, 256, GEMM_SMEM_128>>>(
                p_y, p_w1 + (size_t)L * EMB * FF, nullptr, p_mid, EMB, FF,
                FLAG_GELU | FLAG_HALF);
        }
        {  // w2 split-K=3: partials; reduced in next ln_fused / final lnf
            dim3 grid(EMB / 64, TOK / 128, 3);
            gemm64_sk<<<grid, 128, GEMM_SMEM_64>>>(
                p_mid, p_w2 + (size_t)L * FF * EMB, p_part, FF, FF / 3, EMB);
        }
    }

    // final: h += partials; out = LN_f(h)
    ln_fused<<<TOK, 256>>>(p_h, p_part, lnfs, lnfb, out, 0);
}

// round 15
// speedup vs baseline: 1.1053x; 1.0646x over previous
#include <cuda_runtime.h>
#include <cuda_fp16.h>
#include <math.h>
#include <stdint.h>

#define Bb 2
#define Nn 2048
#define EMB 768
#define NH 12
#define DH 64
#define DEPTH 6
#define FF 3072
#define TOK (Bb * Nn)  // 4096
#define QKVW (3 * EMB) // 2304
#define LN_EPS 1e-6f

// ---------------- scratch (static device globals) ---------------------------
__device__ float g_h[TOK * EMB];
__device__ __half g_y[TOK * EMB];
__device__ __half g_qkv[TOK * 3 * EMB];
__device__ __half g_o[TOK * EMB];
__device__ __half g_mid[TOK * FF];
__device__ float g_part[3 * TOK * EMB];  // split-K partials (wo uses 2, w2 uses 3)
__device__ __half g_wqkv[DEPTH * EMB * 3 * EMB];
__device__ __half g_wo[DEPTH * EMB * EMB];
__device__ __half g_w1[DEPTH * EMB * FF];
__device__ __half g_w2[DEPTH * FF * EMB];

__constant__ float c_slopes[NH] = {
    0.5f, 0.25f, 0.125f, 0.0625f, 0.03125f, 0.015625f, 0.0078125f, 0.00390625f,
    0.70710678118654752f, 0.35355339059327376f, 0.17677669529663688f,
    0.08838834764831844f};

__device__ __forceinline__ void cp16(uint32_t dst, const void* src) {
    asm volatile("cp.async.cg.shared.global [%0], [%1], 16;" ::"r"(dst),
                 "l"(src));
}

__device__ __forceinline__ uint32_t packh2(float a, float b) {
    __half2 h = __floats2half2_rn(a, b);
    return *(uint32_t*)&h;
}

#define MMA_FP16(d, a, b)                                                     \
    asm volatile(                                                             \
        "mma.sync.aligned.m16n8k16.row.col.f32.f16.f16.f32 "                  \
        "{%0,%1,%2,%3},{%4,%5,%6,%7},{%8,%9},{%0,%1,%2,%3};"                  \
        : "+f"(d[0]), "+f"(d[1]), "+f"(d[2]), "+f"(d[3])                      \
        : "r"(a[0]), "r"(a[1]), "r"(a[2]), "r"(a[3]), "r"(b[0]), "r"(b[1]))

#define LDSM_X4(r0, r1, r2, r3, addr)                                        \
    asm volatile(                                                            \
        "ldmatrix.sync.aligned.m8n8.x4.shared.b16 {%0,%1,%2,%3}, [%4];"      \
        : "=r"(r0), "=r"(r1), "=r"(r2), "=r"(r3)                             \
        : "r"(addr))

#define LDSM_X4_T(r0, r1, r2, r3, addr)                                      \
    asm volatile(                                                            \
        "ldmatrix.sync.aligned.m8n8.x4.trans.shared.b16 {%0,%1,%2,%3}, "     \
        "[%4];"                                                              \
        : "=r"(r0), "=r"(r1), "=r"(r2), "=r"(r3)                             \
        : "r"(addr))

// ---------------- copy x -> h ------------------------------------------------
__global__ void copy_kernel(const float* __restrict__ x) {
    int i = blockIdx.x * blockDim.x + threadIdx.x;
    if (i < TOK * EMB) g_h[i] = x[i];
}

// ---------------- fused transpose + fp16 convert of ALL weights -------------
#define TQKV (72 * 24 * DEPTH)
#define TWO (24 * 24 * DEPTH)
#define TW1 (96 * 24 * DEPTH)
#define TW2 (24 * 96 * DEPTH)
#define TALL (TQKV + TWO + TW1 + TW2)

__global__ void transpose_half_all(const float* __restrict__ wqkv,
                                   const float* __restrict__ wo,
                                   const float* __restrict__ w1,
                                   const float* __restrict__ w2,
                                   __half* __restrict__ pwqkv,
                                   __half* __restrict__ pwo,
                                   __half* __restrict__ pw1,
                                   __half* __restrict__ pw2) {
    __shared__ float tile[32][33];
    int b = blockIdx.x;
    const float* W;
    __half* Wt;
    int K, N;
    if (b < TQKV) {
        W = wqkv; Wt = pwqkv; K = EMB; N = 3 * EMB;
    } else if (b < TQKV + TWO) {
        b -= TQKV; W = wo; Wt = pwo; K = EMB; N = EMB;
    } else if (b < TQKV + TWO + TW1) {
        b -= TQKV + TWO; W = w1; Wt = pw1; K = EMB; N = FF;
    } else {
        b -= TQKV + TWO + TW1; W = w2; Wt = pw2; K = FF; N = EMB;
    }
    int ntiles = N / 32, tpl = ntiles * (K / 32);
    int layer = b / tpl, rem = b % tpl;
    int bn = (rem % ntiles) * 32, bk = (rem / ntiles) * 32;
    W += (size_t)layer * K * N;
    Wt += (size_t)layer * K * N;
    int tx = threadIdx.x, ty = threadIdx.y;
#pragma unroll
    for (int i = 0; i < 32; i += 8)
        tile[ty + i][tx] = W[(size_t)(bk + ty + i) * N + bn + tx];
    __syncthreads();
#pragma unroll
    for (int i = 0; i < 32; i += 8)
        Wt[(size_t)(bn + ty + i) * K + bk + tx] =
            __float2half_rn(tile[tx][ty + i]);
}

// ============== vectorized LayerNorm family (192 threads, float4/thread) ====
__device__ __forceinline__ void block_stats_192(float s, float ss, float& mean,
                                                float& inv) {
#pragma unroll
    for (int of = 16; of; of >>= 1) {
        s += __shfl_xor_sync(0xffffffffu, s, of);
        ss += __shfl_xor_sync(0xffffffffu, ss, of);
    }
    __shared__ float sh_s[8], sh_ss[8];
    int w = threadIdx.x >> 5, lane = threadIdx.x & 31;
    if (lane == 0) { sh_s[w] = s; sh_ss[w] = ss; }
    __syncthreads();
    if (threadIdx.x < 32) {
        s = (lane < 6) ? sh_s[lane] : 0.f;
        ss = (lane < 6) ? sh_ss[lane] : 0.f;
#pragma unroll
        for (int of = 4; of; of >>= 1) {
            s += __shfl_xor_sync(0xffffffffu, s, of);
            ss += __shfl_xor_sync(0xffffffffu, ss, of);
        }
        if (lane == 0) { sh_s[0] = s; sh_ss[0] = ss; }
    }
    __syncthreads();
    mean = sh_s[0] * (1.0f / EMB);
    float var = sh_ss[0] * (1.0f / EMB) - mean * mean;
    inv = rsqrtf(var + LN_EPS);
}

__device__ __forceinline__ void ln_write(float4 v, float mean, float inv,
                                         const float* scale,
                                         const float* bias, void* o, int row,
                                         int i, int half_out) {
    float4 sc = ((const float4*)scale)[i];
    float4 bi = ((const float4*)bias)[i];
    float r0 = (v.x - mean) * inv * sc.x + bi.x;
    float r1 = (v.y - mean) * inv * sc.y + bi.y;
    float r2 = (v.z - mean) * inv * sc.z + bi.z;
    float r3 = (v.w - mean) * inv * sc.w + bi.w;
    if (half_out) {
        uint2 u;
        u.x = packh2(r0, r1);
        u.y = packh2(r2, r3);
        ((uint2*)((__half*)o + (size_t)row * EMB))[i] = u;
    } else {
        float4 r;
        r.x = r0; r.y = r1; r.z = r2; r.w = r3;
        ((float4*)((float*)o + (size_t)row * EMB))[i] = r;
    }
}

// plain LN
__global__ void ln_kernel(const float* __restrict__ in,
                          const float* __restrict__ scale,
                          const float* __restrict__ bias, void* __restrict__ o,
                          int half_out) {
    int row = blockIdx.x, i = threadIdx.x;
    float4 v = ((const float4*)(in + (size_t)row * EMB))[i];
    float mean, inv;
    block_stats_192(v.x + v.y + v.z + v.w,
                    v.x * v.x + v.y * v.y + v.z * v.z + v.w * v.w, mean, inv);
    ln_write(v, mean, inv, scale, bias, o, row, i, half_out);
}

// h += p0+p1+p2 (w2 split-K partials), then LN
__global__ void ln_fused(float* __restrict__ h, const float* __restrict__ P,
                         const float* __restrict__ scale,
                         const float* __restrict__ bias, void* __restrict__ o,
                         int half_out) {
    int row = blockIdx.x, i = threadIdx.x;
    float4* hp = (float4*)(h + (size_t)row * EMB);
    const float4* p0 = (const float4*)(P + (size_t)row * EMB);
    const float4* p1 = (const float4*)(P + (size_t)(TOK + row) * EMB);
    const float4* p2 = (const float4*)(P + (size_t)(2 * TOK + row) * EMB);
    float4 v = hp[i], a = p0[i], b = p1[i], c = p2[i];
    v.x += a.x + b.x + c.x;
    v.y += a.y + b.y + c.y;
    v.z += a.z + b.z + c.z;
    v.w += a.w + b.w + c.w;
    hp[i] = v;
    float mean, inv;
    block_stats_192(v.x + v.y + v.z + v.w,
                    v.x * v.x + v.y * v.y + v.z * v.z + v.w * v.w, mean, inv);
    ln_write(v, mean, inv, scale, bias, o, row, i, half_out);
}

// h += p0+p1+bo (wo split-K partials + bias), then LN -> half
__global__ void ln2_fused(float* __restrict__ h, const float* __restrict__ P,
                          const float* __restrict__ bo,
                          const float* __restrict__ scale,
                          const float* __restrict__ bias,
                          __half* __restrict__ o) {
    int row = blockIdx.x, i = threadIdx.x;
    float4* hp = (float4*)(h + (size_t)row * EMB);
    const float4* p0 = (const float4*)(P + (size_t)row * EMB);
    const float4* p1 = (const float4*)(P + (size_t)(TOK + row) * EMB);
    float4 v = hp[i], a = p0[i], b = p1[i];
    float4 bb = ((const float4*)bo)[i];
    v.x += a.x + b.x + bb.x;
    v.y += a.y + b.y + bb.y;
    v.z += a.z + b.z + bb.z;
    v.w += a.w + b.w + bb.w;
    hp[i] = v;
    float mean, inv;
    block_stats_192(v.x + v.y + v.z + v.w,
                    v.x * v.x + v.y * v.y + v.z * v.z + v.w * v.w, mean, inv);
    ln_write(v, mean, inv, scale, bias, o, row, i, 1);
}

#define FLAG_BIAS 1
#define FLAG_GELU 2
#define FLAG_HALF 8

#define STAGES 4
#define A_STAGE 8192

__device__ __forceinline__ float gelu_tanh(float x) {
    const float k0 = 0.7978845608028654f;
    return 0.5f * x * (1.0f + tanhf(k0 * (x + 0.044715f * x * x * x)));
}

// ---------------- split-K gemm: CTA 128x64, z = k-slice, fp32 partial out ---
#define G64_STAGE (A_STAGE + 4096)
#define GEMM_SMEM_64 (STAGES * G64_STAGE)

__global__ __launch_bounds__(128, 4) void gemm64_sk(
    const __half* __restrict__ A, const __half* __restrict__ Wt,
    float* __restrict__ P, int K, int Ksl, int Nout) {
    extern __shared__ char smem[];
    const uint32_t sb = (uint32_t)__cvta_generic_to_shared(smem);
    const int tid = threadIdx.x;
    const int warp = tid >> 5, lane = tid & 31;
    const int wm = warp >> 1, wn = warp & 1;
    const int bm = blockIdx.y * 128, bn = blockIdx.x * 64;
    const int k0 = blockIdx.z * Ksl;
    float* Pz = P + (size_t)blockIdx.z * TOK * EMB;

    const __half* gA = A + (size_t)(bm + tid) * K + k0;
    uint32_t stA[4];
#pragma unroll
    for (int c = 0; c < 4; c++)
        stA[c] = sb + (uint32_t)tid * 64 +
                 (((uint32_t)(c ^ ((tid >> 1) & 3))) << 4);
    const int brow = tid >> 1, bc0 = (tid & 1) * 2;
    const __half* gB = Wt + (size_t)(bn + brow) * K + k0 + bc0 * 8;
    uint32_t stB[2];
#pragma unroll
    for (int i = 0; i < 2; i++)
        stB[i] = sb + A_STAGE + (uint32_t)brow * 64 +
                 (((uint32_t)((bc0 + i) ^ ((brow >> 1) & 3))) << 4);

#define LOAD_S64(s, t_)                                                    \
    do {                                                                   \
        const __half* _a = gA + (t_) * 32;                                 \
        const __half* _b = gB + (t_) * 32;                                 \
        uint32_t _so = (uint32_t)(s)*G64_STAGE;                            \
        _Pragma("unroll") for (int _c = 0; _c < 4; _c++)                   \
            cp16(stA[_c] + _so, _a + _c * 8);                              \
        _Pragma("unroll") for (int _i = 0; _i < 2; _i++)                   \
            cp16(stB[_i] + _so, _b + _i * 8);                              \
        asm volatile("cp.async.commit_group;");                            \
    } while (0)

    int arow7 = lane & 7;
    int a8 = ((lane >> 3) & 1) * 8;
    int acbit = lane >> 4;
    int axor = (arow7 >> 1) & 3;
    uint32_t aBase[4];
#pragma unroll
    for (int mf = 0; mf < 4; mf++)
        aBase[mf] = sb + (uint32_t)(wm * 64 + mf * 16 + arow7 + a8) * 64;
    uint32_t aoff[2];
#pragma unroll
    for (int ks = 0; ks < 2; ks++)
        aoff[ks] = ((uint32_t)((2 * ks + acbit) ^ axor)) << 4;

    int brow7 = lane & 7;
    int bn8 = (lane >> 4) * 8;
    int bcb = (lane >> 3) & 1;
    int bxor = (brow7 >> 1) & 3;
    uint32_t bBase[2];
#pragma unroll
    for (int p = 0; p < 2; p++)
        bBase[p] =
            sb + A_STAGE + (uint32_t)(wn * 32 + p * 16 + brow7 + bn8) * 64;
    uint32_t boff[2];
#pragma unroll
    for (int ks = 0; ks < 2; ks++)
        boff[ks] = ((uint32_t)((2 * ks + bcb) ^ bxor)) << 4;

    float acc[4][4][4];
#pragma unroll
    for (int i = 0; i < 4; i++)
#pragma unroll
        for (int j = 0; j < 4; j++)
#pragma unroll
            for (int c = 0; c < 4; c++) acc[i][j][c] = 0.f;

    const int T = Ksl / 32;
    LOAD_S64(0, 0);
    LOAD_S64(1, 1);
    LOAD_S64(2, 2);

    for (int t = 0; t < T; t++) {
        int rem = ((t + 2 < T) ? (t + 2) : (T - 1)) - t;
        if (rem == 2)
            asm volatile("cp.async.wait_group 2;");
        else if (rem == 1)
            asm volatile("cp.async.wait_group 1;");
        else
            asm volatile("cp.async.wait_group 0;");
        __syncthreads();
        if (t + 3 < T) LOAD_S64((t + 3) & 3, t + 3);

        uint32_t so = (uint32_t)(t & 3) * G64_STAGE;
#pragma unroll
        for (int ks = 0; ks < 2; ks++) {
            uint32_t af[4][4];
#pragma unroll
            for (int mf = 0; mf < 4; mf++)
                LDSM_X4(af[mf][0], af[mf][1], af[mf][2], af[mf][3],
                        aBase[mf] + so + aoff[ks]);
#pragma unroll
            for (int p = 0; p < 2; p++) {
                uint32_t bf0[2], bf1[2];
                LDSM_X4(bf0[0], bf0[1], bf1[0], bf1[1],
                        bBase[p] + so + boff[ks]);
#pragma unroll
                for (int mf = 0; mf < 4; mf++) {
                    MMA_FP16(acc[mf][2 * p], af[mf], bf0);
                    MMA_FP16(acc[mf][2 * p + 1], af[mf], bf1);
                }
            }
        }
    }

    int r = lane >> 2, kq = lane & 3;
#pragma unroll
    for (int mf = 0; mf < 4; mf++) {
#pragma unroll
        for (int nf = 0; nf < 4; nf++) {
            int n0 = bn + wn * 32 + nf * 8 + kq * 2;
#pragma unroll
            for (int half = 0; half < 2; half++) {
                int m0 = bm + wm * 64 + mf * 16 + r + half * 8;
                float2 v;
                v.x = acc[mf][nf][half * 2 + 0];
                v.y = acc[mf][nf][half * 2 + 1];
                *(float2*)&Pz[(size_t)m0 * Nout + n0] = v;
            }
        }
    }
}

// ---------------- fp16 GEMM, CTA 128x128, 256 thr, KT=32, 2 CTA/SM ----------
#define G128_STAGE (A_STAGE + 8192)
#define GEMM_SMEM_128 (STAGES * G128_STAGE)

__global__ __launch_bounds__(256, 2) void gemm128(
    const __half* __restrict__ A, const __half* __restrict__ Wt,
    const float* __restrict__ bias, void* __restrict__ Cv, int K, int Nout,
    int flags) {
    extern __shared__ char smem[];
    const uint32_t sb = (uint32_t)__cvta_generic_to_shared(smem);
    const int tid = threadIdx.x;
    const int warp = tid >> 5, lane = tid & 31;
    const int wm = warp >> 2, wn = warp & 3;
    const int bm = blockIdx.y * 128, bn = blockIdx.x * 128;

    const int srow = tid >> 1, sc0 = (tid & 1) * 2;
    const __half* gA = A + (size_t)(bm + srow) * K + sc0 * 8;
    const __half* gB = Wt + (size_t)(bn + srow) * K + sc0 * 8;
    uint32_t stA[2], stB[2];
#pragma unroll
    for (int i = 0; i < 2; i++) {
        uint32_t off = (uint32_t)srow * 64 +
                       (((uint32_t)((sc0 + i) ^ ((srow >> 1) & 3))) << 4);
        stA[i] = sb + off;
        stB[i] = sb + A_STAGE + off;
    }

#define LOAD_S128(s, t_)                                                   \
    do {                                                                   \
        const __half* _a = gA + (t_) * 32;                                 \
        const __half* _b = gB + (t_) * 32;                                 \
        uint32_t _so = (uint32_t)(s)*G128_STAGE;                           \
        _Pragma("unroll") for (int _i = 0; _i < 2; _i++) {                 \
            cp16(stA[_i] + _so, _a + _i * 8);                              \
            cp16(stB[_i] + _so, _b + _i * 8);                              \
        }                                                                  \
        asm volatile("cp.async.commit_group;");                            \
    } while (0)

    int arow7 = lane & 7;
    int a8 = ((lane >> 3) & 1) * 8;
    int acbit = lane >> 4;
    int axor = (arow7 >> 1) & 3;
    uint32_t aBase[4];
#pragma unroll
    for (int mf = 0; mf < 4; mf++)
        aBase[mf] = sb + (uint32_t)(wm * 64 + mf * 16 + arow7 + a8) * 64;
    uint32_t aoff[2];
#pragma unroll
    for (int ks = 0; ks < 2; ks++)
        aoff[ks] = ((uint32_t)((2 * ks + acbit) ^ axor)) << 4;

    int brow7 = lane & 7;
    int bn8 = (lane >> 4) * 8;
    int bcb = (lane >> 3) & 1;
    int bxor = (brow7 >> 1) & 3;
    uint32_t bBase[2];
#pragma unroll
    for (int p = 0; p < 2; p++)
        bBase[p] =
            sb + A_STAGE + (uint32_t)(wn * 32 + p * 16 + brow7 + bn8) * 64;
    uint32_t boff[2];
#pragma unroll
    for (int ks = 0; ks < 2; ks++)
        boff[ks] = ((uint32_t)((2 * ks + bcb) ^ bxor)) << 4;

    float acc[4][4][4];
#pragma unroll
    for (int i = 0; i < 4; i++)
#pragma unroll
        for (int j = 0; j < 4; j++)
#pragma unroll
            for (int c = 0; c < 4; c++) acc[i][j][c] = 0.f;

    const int T = K / 32;
    LOAD_S128(0, 0);
    LOAD_S128(1, 1);
    LOAD_S128(2, 2);

    for (int t = 0; t < T; t++) {
        int rem = ((t + 2 < T) ? (t + 2) : (T - 1)) - t;
        if (rem == 2)
            asm volatile("cp.async.wait_group 2;");
        else if (rem == 1)
            asm volatile("cp.async.wait_group 1;");
        else
            asm volatile("cp.async.wait_group 0;");
        __syncthreads();
        if (t + 3 < T) LOAD_S128((t + 3) & 3, t + 3);

        uint32_t so = (uint32_t)(t & 3) * G128_STAGE;
#pragma unroll
        for (int ks = 0; ks < 2; ks++) {
            uint32_t af[4][4];
#pragma unroll
            for (int mf = 0; mf < 4; mf++)
                LDSM_X4(af[mf][0], af[mf][1], af[mf][2], af[mf][3],
                        aBase[mf] + so + aoff[ks]);
#pragma unroll
            for (int p = 0; p < 2; p++) {
                uint32_t bf0[2], bf1[2];
                LDSM_X4(bf0[0], bf0[1], bf1[0], bf1[1],
                        bBase[p] + so + boff[ks]);
#pragma unroll
                for (int mf = 0; mf < 4; mf++) {
                    MMA_FP16(acc[mf][2 * p], af[mf], bf0);
                    MMA_FP16(acc[mf][2 * p + 1], af[mf], bf1);
                }
            }
        }
    }

    int r = lane >> 2, kq = lane & 3;
#pragma unroll
    for (int mf = 0; mf < 4; mf++) {
#pragma unroll
        for (int nf = 0; nf < 4; nf++) {
            int n0 = bn + wn * 32 + nf * 8 + kq * 2;
#pragma unroll
            for (int half = 0; half < 2; half++) {
                int m0 = bm + wm * 64 + mf * 16 + r + half * 8;
                float2 v;
                v.x = acc[mf][nf][half * 2 + 0];
                v.y = acc[mf][nf][half * 2 + 1];
                if (flags & FLAG_BIAS) {
                    v.x += bias[n0];
                    v.y += bias[n0 + 1];
                }
                if (flags & FLAG_GELU) {
                    v.x = gelu_tanh(v.x);
                    v.y = gelu_tanh(v.y);
                }
                if (flags & FLAG_HALF) {
                    __half2* dst =
                        (__half2*)((__half*)Cv + (size_t)m0 * Nout + n0);
                    *dst = __floats2half2_rn(v.x, v.y);
                } else {
                    float2* dst =
                        (float2*)((float*)Cv + (size_t)m0 * Nout + n0);
                    *dst = v;
                }
            }
        }
    }
}

// ---------------- flash attention w/ tensor cores (causal + ALiBi) ----------
__global__ __launch_bounds__(128) void attn_mma(const __half* __restrict__ qkv,
                                                __half* __restrict__ out) {
    __shared__ __align__(16) char smem[40960];
    const uint32_t sb = (uint32_t)__cvta_generic_to_shared(smem);
    const int tid = threadIdx.x;
    const int w = tid >> 5, lane = tid & 31;
    // heavy (high qt) CTAs first: reduces makespan tail at ~1 wave occupancy
    const int qt = gridDim.x - 1 - blockIdx.x;
    const int bh = blockIdx.y;
    const int b = bh / NH, h = bh % NH;
    const float slope = c_slopes[h];

    const int srow = tid >> 1, c0 = (tid & 1) * 4;
    const int sxor = srow & 7;
    const uint32_t rowoff = sb + (uint32_t)srow * 128;

    {
        const __half* gQ = qkv +
                           (size_t)(b * Nn + qt * 64 + srow) * QKVW + h * DH +
                           c0 * 8;
#pragma unroll
        for (int i = 0; i < 4; i++)
            cp16(rowoff + (((uint32_t)((c0 + i) ^ sxor)) << 4), gQ + i * 8);
        asm volatile("cp.async.commit_group;");
    }

#define LOAD_KV(kt_, buf_)                                                   \
    do {                                                                     \
        const __half* _gK = qkv +                                            \
                            (size_t)(b * Nn + (kt_)*64 + srow) * QKVW + EMB + \
                            h * DH + c0 * 8;                                 \
        uint32_t _base = rowoff + 8192 + (uint32_t)(buf_)*16384;             \
        _Pragma("unroll") for (int _i = 0; _i < 4; _i++)                     \
            cp16(_base + (((uint32_t)((c0 + _i) ^ sxor)) << 4), _gK + _i * 8); \
        _Pragma("unroll") for (int _i = 0; _i < 4; _i++)                     \
            cp16(_base + 8192 + (((uint32_t)((c0 + _i) ^ sxor)) << 4),       \
                 _gK + EMB + _i * 8);                                        \
        asm volatile("cp.async.commit_group;");                              \
    } while (0)

    LOAD_KV(0, 0);

    asm volatile("cp.async.wait_group 1;");
    __syncthreads();
    const int arow7 = lane & 7;
    const int a8 = ((lane >> 3) & 1) * 8;
    const int acbit = lane >> 4;
    uint32_t Qf[4][4];
    {
        uint32_t qrow = (uint32_t)(w * 16 + arow7 + a8);
        uint32_t qaddr = sb + qrow * 128;
#pragma unroll
        for (int kc = 0; kc < 4; kc++)
            LDSM_X4(Qf[kc][0], Qf[kc][1], Qf[kc][2], Qf[kc][3],
                    qaddr + (((uint32_t)((2 * kc + acbit) ^ arow7)) << 4));
    }

    const int r = lane >> 2, kq = lane & 3;
    const int row0 = qt * 64 + w * 16 + r;
    const int row1 = row0 + 8;
    float m0 = -1e30f, m1 = -1e30f, l0 = 0.f, l1 = 0.f;
    float O[8][4];
#pragma unroll
    for (int dt = 0; dt < 8; dt++)
#pragma unroll
        for (int c = 0; c < 4; c++) O[dt][c] = 0.f;

    const int bg = lane >> 3;
    const int bcb = bg & 1;
    const int brofs = (bg >> 1) * 8;
    const int brow7 = lane & 7;
    const uint32_t vrowlocal = (uint32_t)((lane & 7) + ((lane >> 3) & 1) * 8);
    const int vcbit = lane >> 4;

    for (int kt = 0; kt <= qt; kt++) {
        int buf = kt & 1;
        if (kt < qt) LOAD_KV(kt + 1, buf ^ 1);
        if (kt < qt)
            asm volatile("cp.async.wait_group 1;");
        else
            asm volatile("cp.async.wait_group 0;");
        __syncthreads();

        uint32_t kbase = sb + 8192 + (uint32_t)buf * 16384;
        uint32_t vbase = kbase + 8192;

        float S[8][4];
#pragma unroll
        for (int nt = 0; nt < 8; nt++)
#pragma unroll
            for (int c = 0; c < 4; c++) S[nt][c] = 0.f;
#pragma unroll
        for (int kc = 0; kc < 4; kc++) {
            uint32_t bf[8][2];
#pragma unroll
            for (int p = 0; p < 4; p++) {
                uint32_t rr = (uint32_t)(p * 16 + brofs + brow7);
                LDSM_X4(bf[2 * p][0], bf[2 * p][1], bf[2 * p + 1][0],
                        bf[2 * p + 1][1],
                        kbase + rr * 128 +
                            (((uint32_t)((2 * kc + bcb) ^ brow7)) << 4));
            }
#pragma unroll
            for (int nt = 0; nt < 8; nt++) MMA_FP16(S[nt], Qf[kc], bf[nt]);
        }

        bool diag = (kt == qt);
        float mx0 = -1e30f, mx1 = -1e30f;
#pragma unroll
        for (int nt = 0; nt < 8; nt++) {
            int colb = kt * 64 + nt * 8 + kq * 2;
#pragma unroll
            for (int c = 0; c < 4; c++) {
                int col = colb + (c & 1);
                float v = S[nt][c] * 0.125f + slope * (float)col;
                if (diag && col > ((c < 2) ? row0 : row1)) v = -1e30f;
                S[nt][c] = v;
                if (c < 2)
                    mx0 = fmaxf(mx0, v);
                else
                    mx1 = fmaxf(mx1, v);
            }
        }
        mx0 = fmaxf(mx0, __shfl_xor_sync(0xffffffffu, mx0, 1));
        mx0 = fmaxf(mx0, __shfl_xor_sync(0xffffffffu, mx0, 2));
        mx1 = fmaxf(mx1, __shfl_xor_sync(0xffffffffu, mx1, 1));
        mx1 = fmaxf(mx1, __shfl_xor_sync(0xffffffffu, mx1, 2));

        float nm0 = fmaxf(m0, mx0), nm1 = fmaxf(m1, mx1);
        float corr0 = __expf(m0 - nm0), corr1 = __expf(m1 - nm1);
        m0 = nm0;
        m1 = nm1;

        float sum0 = 0.f, sum1 = 0.f;
#pragma unroll
        for (int nt = 0; nt < 8; nt++) {
            float p0 = __expf(S[nt][0] - m0);
            float p1 = __expf(S[nt][1] - m0);
            float p2 = __expf(S[nt][2] - m1);
            float p3 = __expf(S[nt][3] - m1);
            S[nt][0] = p0;
            S[nt][1] = p1;
            S[nt][2] = p2;
            S[nt][3] = p3;
            sum0 += p0 + p1;
            sum1 += p2 + p3;
        }
        sum0 += __shfl_xor_sync(0xffffffffu, sum0, 1);
        sum0 += __shfl_xor_sync(0xffffffffu, sum0, 2);
        sum1 += __shfl_xor_sync(0xffffffffu, sum1, 1);
        sum1 += __shfl_xor_sync(0xffffffffu, sum1, 2);
        l0 = l0 * corr0 + sum0;
        l1 = l1 * corr1 + sum1;

#pragma unroll
        for (int dt = 0; dt < 8; dt++) {
            O[dt][0] *= corr0;
            O[dt][1] *= corr0;
            O[dt][2] *= corr1;
            O[dt][3] *= corr1;
        }

#pragma unroll
        for (int kc2 = 0; kc2 < 4; kc2++) {
            uint32_t aP[4];
            aP[0] = packh2(S[2 * kc2][0], S[2 * kc2][1]);
            aP[1] = packh2(S[2 * kc2][2], S[2 * kc2][3]);
            aP[2] = packh2(S[2 * kc2 + 1][0], S[2 * kc2 + 1][1]);
            aP[3] = packh2(S[2 * kc2 + 1][2], S[2 * kc2 + 1][3]);
            uint32_t vrow = (uint32_t)(kc2 * 16) + vrowlocal;
            uint32_t vra = vbase + vrow * 128;
            uint32_t vswz = vrow & 7;
#pragma unroll
            for (int cc = 0; cc < 4; cc++) {
                uint32_t v0, v1, v2, v3;
                LDSM_X4_T(v0, v1, v2, v3,
                          vra + (((uint32_t)((2 * cc + vcbit) ^ vswz)) << 4));
                uint32_t bA[2] = {v0, v1}, bB[2] = {v2, v3};
                MMA_FP16(O[2 * cc], aP, bA);
                MMA_FP16(O[2 * cc + 1], aP, bB);
            }
        }
        __syncthreads();
    }

    float i0 = 1.0f / l0, i1 = 1.0f / l1;
    __half* o0 = out + (size_t)(b * Nn + row0) * EMB + h * DH + kq * 2;
    __half* o1 = out + (size_t)(b * Nn + row1) * EMB + h * DH + kq * 2;
#pragma unroll
    for (int dt = 0; dt < 8; dt++) {
        *(__half2*)(o0 + dt * 8) =
            __floats2half2_rn(O[dt][0] * i0, O[dt][1] * i0);
        *(__half2*)(o1 + dt * 8) =
            __floats2half2_rn(O[dt][2] * i1, O[dt][3] * i1);
    }
}

// ---------------- host orchestration -----------------------------------------
extern "C" void kernel_launch(void* const* d_in, const int* in_sizes, int n_in,
                              void* d_out, int out_size) {
    const float* x = (const float*)d_in[0];
    const float* wqkv = (const float*)d_in[1];
    const float* bqkv = (const float*)d_in[2];
    const float* wo = (const float*)d_in[3];
    const float* bo = (const float*)d_in[4];
    const float* ln1s = (const float*)d_in[5];
    const float* ln1b = (const float*)d_in[6];
    const float* ln2s = (const float*)d_in[7];
    const float* ln2b = (const float*)d_in[8];
    const float* w1 = (const float*)d_in[9];
    const float* w2 = (const float*)d_in[10];
    const float* lnfs = (const float*)d_in[11];
    const float* lnfb = (const float*)d_in[12];
    float* out = (float*)d_out;

    float *p_h, *p_part;
    __half *p_y, *p_qkv, *p_o, *p_mid, *p_wqkv, *p_wo, *p_w1, *p_w2;
    cudaGetSymbolAddress((void**)&p_h, g_h);
    cudaGetSymbolAddress((void**)&p_part, g_part);
    cudaGetSymbolAddress((void**)&p_y, g_y);
    cudaGetSymbolAddress((void**)&p_qkv, g_qkv);
    cudaGetSymbolAddress((void**)&p_o, g_o);
    cudaGetSymbolAddress((void**)&p_mid, g_mid);
    cudaGetSymbolAddress((void**)&p_wqkv, g_wqkv);
    cudaGetSymbolAddress((void**)&p_wo, g_wo);
    cudaGetSymbolAddress((void**)&p_w1, g_w1);
    cudaGetSymbolAddress((void**)&p_w2, g_w2);

    cudaFuncSetAttribute(gemm64_sk, cudaFuncAttributeMaxDynamicSharedMemorySize,
                         GEMM_SMEM_64);
    cudaFuncSetAttribute(gemm128, cudaFuncAttributeMaxDynamicSharedMemorySize,
                         GEMM_SMEM_128);

    copy_kernel<<<(TOK * EMB + 255) / 256, 256>>>(x);

    transpose_half_all<<<TALL, dim3(32, 8)>>>(wqkv, wo, w1, w2, p_wqkv, p_wo,
                                              p_w1, p_w2);

    for (int L = 0; L < DEPTH; L++) {
        if (L == 0)
            ln_kernel<<<TOK, 192>>>(p_h, ln1s, ln1b, p_y, 1);
        else
            ln_fused<<<TOK, 192>>>(p_h, p_part, ln1s + L * EMB, ln1b + L * EMB,
                                   p_y, 1);
        {  // qkv = y @ Wqkv + b (fp16 out)
            dim3 grid(3 * EMB / 128, TOK / 128);
            gemm128<<<grid, 256, GEMM_SMEM_128>>>(
                p_y, p_wqkv + (size_t)L * EMB * 3 * EMB, bqkv + L * 3 * EMB,
                p_qkv, EMB, 3 * EMB, FLAG_BIAS | FLAG_HALF);
        }
        {  // flash attention (heavy tiles first)
            dim3 grid(Nn / 64, Bb * NH);
            attn_mma<<<grid, 128>>>(p_qkv, p_o);
        }
        {  // wo split-K=2: partials (reduced in ln2_fused with bias)
            dim3 grid(EMB / 64, TOK / 128, 2);
            gemm64_sk<<<grid, 128, GEMM_SMEM_64>>>(
                p_o, p_wo + (size_t)L * EMB * EMB, p_part, EMB, EMB / 2, EMB);
        }
        // h += wo partials + bo; y = LN2(h)
        ln2_fused<<<TOK, 192>>>(p_h, p_part, bo + L * EMB, ln2s + L * EMB,
                                ln2b + L * EMB, p_y);
        {  // mid = gelu(y @ W1) (half out)
            dim3 grid(FF / 128, TOK / 128);
            gemm128<<<grid, 256, GEMM_SMEM_128>>>(
                p_y, p_w1 + (size_t)L * EMB * FF, nullptr, p_mid, EMB, FF,
                FLAG_GELU | FLAG_HALF);
        }
        {  // w2 split-K=3: partials; reduced in next ln_fused / final lnf
            dim3 grid(EMB / 64, TOK / 128, 3);
            gemm64_sk<<<grid, 128, GEMM_SMEM_64>>>(
                p_mid, p_w2 + (size_t)L * FF * EMB, p_part, FF, FF / 3, EMB);
        }
    }

    // final: h += w2 partials; out = LN_f(h)
    ln_fused<<<TOK, 192>>>(p_h, p_part, lnfs, lnfb, out, 0);
}

// round 16
// speedup vs baseline: 1.1083x; 1.0027x over previous
#include <cuda_runtime.h>
#include <cuda_fp16.h>
#include <math.h>
#include <stdint.h>

#define Bb 2
#define Nn 2048
#define EMB 768
#define NH 12
#define DH 64
#define DEPTH 6
#define FF 3072
#define TOK (Bb * Nn)  // 4096
#define QKVW (3 * EMB) // 2304
#define LN_EPS 1e-6f

// ---------------- scratch (static device globals) ---------------------------
__device__ float g_h[TOK * EMB];
__device__ __half g_y[TOK * EMB];
__device__ __half g_qkv[TOK * 3 * EMB];
__device__ __half g_o[TOK * EMB];
__device__ __half g_mid[TOK * FF];
__device__ float g_part[3 * TOK * EMB];
__device__ __half g_wqkv[DEPTH * EMB * 3 * EMB];
__device__ __half g_wo[DEPTH * EMB * EMB];
__device__ __half g_w1[DEPTH * EMB * FF];
__device__ __half g_w2[DEPTH * FF * EMB];

__constant__ float c_slopes[NH] = {
    0.5f, 0.25f, 0.125f, 0.0625f, 0.03125f, 0.015625f, 0.0078125f, 0.00390625f,
    0.70710678118654752f, 0.35355339059327376f, 0.17677669529663688f,
    0.08838834764831844f};

__device__ __forceinline__ void cp16(uint32_t dst, const void* src) {
    asm volatile("cp.async.cg.shared.global [%0], [%1], 16;" ::"r"(dst),
                 "l"(src));
}

__device__ __forceinline__ uint32_t packh2(float a, float b) {
    __half2 h = __floats2half2_rn(a, b);
    return *(uint32_t*)&h;
}

#define MMA_FP16(d, a, b)                                                     \
    asm volatile(                                                             \
        "mma.sync.aligned.m16n8k16.row.col.f32.f16.f16.f32 "                  \
        "{%0,%1,%2,%3},{%4,%5,%6,%7},{%8,%9},{%0,%1,%2,%3};"                  \
        : "+f"(d[0]), "+f"(d[1]), "+f"(d[2]), "+f"(d[3])                      \
        : "r"(a[0]), "r"(a[1]), "r"(a[2]), "r"(a[3]), "r"(b[0]), "r"(b[1]))

#define LDSM_X4(r0, r1, r2, r3, addr)                                        \
    asm volatile(                                                            \
        "ldmatrix.sync.aligned.m8n8.x4.shared.b16 {%0,%1,%2,%3}, [%4];"      \
        : "=r"(r0), "=r"(r1), "=r"(r2), "=r"(r3)                             \
        : "r"(addr))

#define LDSM_X4_T(r0, r1, r2, r3, addr)                                      \
    asm volatile(                                                            \
        "ldmatrix.sync.aligned.m8n8.x4.trans.shared.b16 {%0,%1,%2,%3}, "     \
        "[%4];"                                                              \
        : "=r"(r0), "=r"(r1), "=r"(r2), "=r"(r3)                             \
        : "r"(addr))

// ---------------- fused transpose + fp16 convert of ALL weights -------------
#define TQKV (72 * 24 * DEPTH)
#define TWO (24 * 24 * DEPTH)
#define TW1 (96 * 24 * DEPTH)
#define TW2 (24 * 96 * DEPTH)
#define TALL (TQKV + TWO + TW1 + TW2)

__global__ void transpose_half_all(const float* __restrict__ wqkv,
                                   const float* __restrict__ wo,
                                   const float* __restrict__ w1,
                                   const float* __restrict__ w2,
                                   __half* __restrict__ pwqkv,
                                   __half* __restrict__ pwo,
                                   __half* __restrict__ pw1,
                                   __half* __restrict__ pw2) {
    __shared__ float tile[32][33];
    int b = blockIdx.x;
    const float* W;
    __half* Wt;
    int K, N;
    if (b < TQKV) {
        W = wqkv; Wt = pwqkv; K = EMB; N = 3 * EMB;
    } else if (b < TQKV + TWO) {
        b -= TQKV; W = wo; Wt = pwo; K = EMB; N = EMB;
    } else if (b < TQKV + TWO + TW1) {
        b -= TQKV + TWO; W = w1; Wt = pw1; K = EMB; N = FF;
    } else {
        b -= TQKV + TWO + TW1; W = w2; Wt = pw2; K = FF; N = EMB;
    }
    int ntiles = N / 32, tpl = ntiles * (K / 32);
    int layer = b / tpl, rem = b % tpl;
    int bn = (rem % ntiles) * 32, bk = (rem / ntiles) * 32;
    W += (size_t)layer * K * N;
    Wt += (size_t)layer * K * N;
    int tx = threadIdx.x, ty = threadIdx.y;
#pragma unroll
    for (int i = 0; i < 32; i += 8)
        tile[ty + i][tx] = W[(size_t)(bk + ty + i) * N + bn + tx];
    __syncthreads();
#pragma unroll
    for (int i = 0; i < 32; i += 8)
        Wt[(size_t)(bn + ty + i) * K + bk + tx] =
            __float2half_rn(tile[tx][ty + i]);
}

// ============== vectorized LayerNorm family (192 threads, float4/thread) ====
__device__ __forceinline__ void block_stats_192(float s, float ss, float& mean,
                                                float& inv) {
#pragma unroll
    for (int of = 16; of; of >>= 1) {
        s += __shfl_xor_sync(0xffffffffu, s, of);
        ss += __shfl_xor_sync(0xffffffffu, ss, of);
    }
    __shared__ float sh_s[8], sh_ss[8];
    int w = threadIdx.x >> 5, lane = threadIdx.x & 31;
    if (lane == 0) { sh_s[w] = s; sh_ss[w] = ss; }
    __syncthreads();
    if (threadIdx.x < 32) {
        s = (lane < 6) ? sh_s[lane] : 0.f;
        ss = (lane < 6) ? sh_ss[lane] : 0.f;
#pragma unroll
        for (int of = 4; of; of >>= 1) {
            s += __shfl_xor_sync(0xffffffffu, s, of);
            ss += __shfl_xor_sync(0xffffffffu, ss, of);
        }
        if (lane == 0) { sh_s[0] = s; sh_ss[0] = ss; }
    }
    __syncthreads();
    mean = sh_s[0] * (1.0f / EMB);
    float var = sh_ss[0] * (1.0f / EMB) - mean * mean;
    inv = rsqrtf(var + LN_EPS);
}

__device__ __forceinline__ void ln_write(float4 v, float mean, float inv,
                                         const float* scale,
                                         const float* bias, void* o, int row,
                                         int i, int half_out) {
    float4 sc = ((const float4*)scale)[i];
    float4 bi = ((const float4*)bias)[i];
    float r0 = (v.x - mean) * inv * sc.x + bi.x;
    float r1 = (v.y - mean) * inv * sc.y + bi.y;
    float r2 = (v.z - mean) * inv * sc.z + bi.z;
    float r3 = (v.w - mean) * inv * sc.w + bi.w;
    if (half_out) {
        uint2 u;
        u.x = packh2(r0, r1);
        u.y = packh2(r2, r3);
        ((uint2*)((__half*)o + (size_t)row * EMB))[i] = u;
    } else {
        float4 r;
        r.x = r0; r.y = r1; r.z = r2; r.w = r3;
        ((float4*)((float*)o + (size_t)row * EMB))[i] = r;
    }
}

// layer-0 LN: reads x, initializes h = x, writes LN(x) -> y (half)
__global__ void ln0_kernel(const float* __restrict__ x,
                           float* __restrict__ h,
                           const float* __restrict__ scale,
                           const float* __restrict__ bias,
                           __half* __restrict__ o) {
    int row = blockIdx.x, i = threadIdx.x;
    float4 v = ((const float4*)(x + (size_t)row * EMB))[i];
    ((float4*)(h + (size_t)row * EMB))[i] = v;
    float mean, inv;
    block_stats_192(v.x + v.y + v.z + v.w,
                    v.x * v.x + v.y * v.y + v.z * v.z + v.w * v.w, mean, inv);
    ln_write(v, mean, inv, scale, bias, o, row, i, 1);
}

// h += p0+p1+p2 (w2 split-K partials), then LN
__global__ void ln_fused(float* __restrict__ h, const float* __restrict__ P,
                         const float* __restrict__ scale,
                         const float* __restrict__ bias, void* __restrict__ o,
                         int half_out) {
    int row = blockIdx.x, i = threadIdx.x;
    float4* hp = (float4*)(h + (size_t)row * EMB);
    const float4* p0 = (const float4*)(P + (size_t)row * EMB);
    const float4* p1 = (const float4*)(P + (size_t)(TOK + row) * EMB);
    const float4* p2 = (const float4*)(P + (size_t)(2 * TOK + row) * EMB);
    float4 v = hp[i], a = p0[i], b = p1[i], c = p2[i];
    v.x += a.x + b.x + c.x;
    v.y += a.y + b.y + c.y;
    v.z += a.z + b.z + c.z;
    v.w += a.w + b.w + c.w;
    hp[i] = v;
    float mean, inv;
    block_stats_192(v.x + v.y + v.z + v.w,
                    v.x * v.x + v.y * v.y + v.z * v.z + v.w * v.w, mean, inv);
    ln_write(v, mean, inv, scale, bias, o, row, i, half_out);
}

// h += p0+p1+bo (wo split-K partials + bias), then LN -> half
__global__ void ln2_fused(float* __restrict__ h, const float* __restrict__ P,
                          const float* __restrict__ bo,
                          const float* __restrict__ scale,
                          const float* __restrict__ bias,
                          __half* __restrict__ o) {
    int row = blockIdx.x, i = threadIdx.x;
    float4* hp = (float4*)(h + (size_t)row * EMB);
    const float4* p0 = (const float4*)(P + (size_t)row * EMB);
    const float4* p1 = (const float4*)(P + (size_t)(TOK + row) * EMB);
    float4 v = hp[i], a = p0[i], b = p1[i];
    float4 bb = ((const float4*)bo)[i];
    v.x += a.x + b.x + bb.x;
    v.y += a.y + b.y + bb.y;
    v.z += a.z + b.z + bb.z;
    v.w += a.w + b.w + bb.w;
    hp[i] = v;
    float mean, inv;
    block_stats_192(v.x + v.y + v.z + v.w,
                    v.x * v.x + v.y * v.y + v.z * v.z + v.w * v.w, mean, inv);
    ln_write(v, mean, inv, scale, bias, o, row, i, 1);
}

#define FLAG_BIAS 1
#define FLAG_GELU 2
#define FLAG_HALF 8

#define STAGES 4
#define A_STAGE 8192

__device__ __forceinline__ float gelu_tanh(float x) {
    const float k0 = 0.7978845608028654f;
    return 0.5f * x * (1.0f + tanhf(k0 * (x + 0.044715f * x * x * x)));
}

// ---------------- split-K gemm: CTA 128x64, z = k-slice, fp32 partial out ---
#define G64_STAGE (A_STAGE + 4096)
#define GEMM_SMEM_64 (STAGES * G64_STAGE)

__global__ __launch_bounds__(128, 4) void gemm64_sk(
    const __half* __restrict__ A, const __half* __restrict__ Wt,
    float* __restrict__ P, int K, int Ksl, int Nout) {
    extern __shared__ char smem[];
    const uint32_t sb = (uint32_t)__cvta_generic_to_shared(smem);
    const int tid = threadIdx.x;
    const int warp = tid >> 5, lane = tid & 31;
    const int wm = warp >> 1, wn = warp & 1;
    const int bm = blockIdx.y * 128, bn = blockIdx.x * 64;
    const int k0 = blockIdx.z * Ksl;
    float* Pz = P + (size_t)blockIdx.z * TOK * EMB;

    const __half* gA = A + (size_t)(bm + tid) * K + k0;
    uint32_t stA[4];
#pragma unroll
    for (int c = 0; c < 4; c++)
        stA[c] = sb + (uint32_t)tid * 64 +
                 (((uint32_t)(c ^ ((tid >> 1) & 3))) << 4);
    const int brow = tid >> 1, bc0 = (tid & 1) * 2;
    const __half* gB = Wt + (size_t)(bn + brow) * K + k0 + bc0 * 8;
    uint32_t stB[2];
#pragma unroll
    for (int i = 0; i < 2; i++)
        stB[i] = sb + A_STAGE + (uint32_t)brow * 64 +
                 (((uint32_t)((bc0 + i) ^ ((brow >> 1) & 3))) << 4);

#define LOAD_S64(s, t_)                                                    \
    do {                                                                   \
        const __half* _a = gA + (t_) * 32;                                 \
        const __half* _b = gB + (t_) * 32;                                 \
        uint32_t _so = (uint32_t)(s)*G64_STAGE;                            \
        _Pragma("unroll") for (int _c = 0; _c < 4; _c++)                   \
            cp16(stA[_c] + _so, _a + _c * 8);                              \
        _Pragma("unroll") for (int _i = 0; _i < 2; _i++)                   \
            cp16(stB[_i] + _so, _b + _i * 8);                              \
        asm volatile("cp.async.commit_group;");                            \
    } while (0)

    int arow7 = lane & 7;
    int a8 = ((lane >> 3) & 1) * 8;
    int acbit = lane >> 4;
    int axor = (arow7 >> 1) & 3;
    uint32_t aBase[4];
#pragma unroll
    for (int mf = 0; mf < 4; mf++)
        aBase[mf] = sb + (uint32_t)(wm * 64 + mf * 16 + arow7 + a8) * 64;
    uint32_t aoff[2];
#pragma unroll
    for (int ks = 0; ks < 2; ks++)
        aoff[ks] = ((uint32_t)((2 * ks + acbit) ^ axor)) << 4;

    int brow7 = lane & 7;
    int bn8 = (lane >> 4) * 8;
    int bcb = (lane >> 3) & 1;
    int bxor = (brow7 >> 1) & 3;
    uint32_t bBase[2];
#pragma unroll
    for (int p = 0; p < 2; p++)
        bBase[p] =
            sb + A_STAGE + (uint32_t)(wn * 32 + p * 16 + brow7 + bn8) * 64;
    uint32_t boff[2];
#pragma unroll
    for (int ks = 0; ks < 2; ks++)
        boff[ks] = ((uint32_t)((2 * ks + bcb) ^ bxor)) << 4;

    float acc[4][4][4];
#pragma unroll
    for (int i = 0; i < 4; i++)
#pragma unroll
        for (int j = 0; j < 4; j++)
#pragma unroll
            for (int c = 0; c < 4; c++) acc[i][j][c] = 0.f;

    const int T = Ksl / 32;
    LOAD_S64(0, 0);
    LOAD_S64(1, 1);
    LOAD_S64(2, 2);

    for (int t = 0; t < T; t++) {
        int rem = ((t + 2 < T) ? (t + 2) : (T - 1)) - t;
        if (rem == 2)
            asm volatile("cp.async.wait_group 2;");
        else if (rem == 1)
            asm volatile("cp.async.wait_group 1;");
        else
            asm volatile("cp.async.wait_group 0;");
        __syncthreads();
        if (t + 3 < T) LOAD_S64((t + 3) & 3, t + 3);

        uint32_t so = (uint32_t)(t & 3) * G64_STAGE;
        // full-tile fragment prefetch: all LDSMs before any MMA
        uint32_t af[2][4][4], bf[2][4][2];
#pragma unroll
        for (int ks = 0; ks < 2; ks++) {
#pragma unroll
            for (int mf = 0; mf < 4; mf++)
                LDSM_X4(af[ks][mf][0], af[ks][mf][1], af[ks][mf][2],
                        af[ks][mf][3], aBase[mf] + so + aoff[ks]);
#pragma unroll
            for (int p = 0; p < 2; p++)
                LDSM_X4(bf[ks][2 * p][0], bf[ks][2 * p][1],
                        bf[ks][2 * p + 1][0], bf[ks][2 * p + 1][1],
                        bBase[p] + so + boff[ks]);
        }
#pragma unroll
        for (int ks = 0; ks < 2; ks++)
#pragma unroll
            for (int mf = 0; mf < 4; mf++)
#pragma unroll
                for (int nf = 0; nf < 4; nf++)
                    MMA_FP16(acc[mf][nf], af[ks][mf], bf[ks][nf]);
    }

    int r = lane >> 2, kq = lane & 3;
#pragma unroll
    for (int mf = 0; mf < 4; mf++) {
#pragma unroll
        for (int nf = 0; nf < 4; nf++) {
            int n0 = bn + wn * 32 + nf * 8 + kq * 2;
#pragma unroll
            for (int half = 0; half < 2; half++) {
                int m0 = bm + wm * 64 + mf * 16 + r + half * 8;
                float2 v;
                v.x = acc[mf][nf][half * 2 + 0];
                v.y = acc[mf][nf][half * 2 + 1];
                *(float2*)&Pz[(size_t)m0 * Nout + n0] = v;
            }
        }
    }
}

// ---------------- fp16 GEMM, CTA 128x128, 256 thr, KT=32, 2 CTA/SM ----------
#define G128_STAGE (A_STAGE + 8192)
#define GEMM_SMEM_128 (STAGES * G128_STAGE)

__global__ __launch_bounds__(256, 2) void gemm128(
    const __half* __restrict__ A, const __half* __restrict__ Wt,
    const float* __restrict__ bias, void* __restrict__ Cv, int K, int Nout,
    int flags) {
    extern __shared__ char smem[];
    const uint32_t sb = (uint32_t)__cvta_generic_to_shared(smem);
    const int tid = threadIdx.x;
    const int warp = tid >> 5, lane = tid & 31;
    const int wm = warp >> 2, wn = warp & 3;
    const int bm = blockIdx.y * 128, bn = blockIdx.x * 128;

    const int srow = tid >> 1, sc0 = (tid & 1) * 2;
    const __half* gA = A + (size_t)(bm + srow) * K + sc0 * 8;
    const __half* gB = Wt + (size_t)(bn + srow) * K + sc0 * 8;
    uint32_t stA[2], stB[2];
#pragma unroll
    for (int i = 0; i < 2; i++) {
        uint32_t off = (uint32_t)srow * 64 +
                       (((uint32_t)((sc0 + i) ^ ((srow >> 1) & 3))) << 4);
        stA[i] = sb + off;
        stB[i] = sb + A_STAGE + off;
    }

#define LOAD_S128(s, t_)                                                   \
    do {                                                                   \
        const __half* _a = gA + (t_) * 32;                                 \
        const __half* _b = gB + (t_) * 32;                                 \
        uint32_t _so = (uint32_t)(s)*G128_STAGE;                           \
        _Pragma("unroll") for (int _i = 0; _i < 2; _i++) {                 \
            cp16(stA[_i] + _so, _a + _i * 8);                              \
            cp16(stB[_i] + _so, _b + _i * 8);                              \
        }                                                                  \
        asm volatile("cp.async.commit_group;");                            \
    } while (0)

    int arow7 = lane & 7;
    int a8 = ((lane >> 3) & 1) * 8;
    int acbit = lane >> 4;
    int axor = (arow7 >> 1) & 3;
    uint32_t aBase[4];
#pragma unroll
    for (int mf = 0; mf < 4; mf++)
        aBase[mf] = sb + (uint32_t)(wm * 64 + mf * 16 + arow7 + a8) * 64;
    uint32_t aoff[2];
#pragma unroll
    for (int ks = 0; ks < 2; ks++)
        aoff[ks] = ((uint32_t)((2 * ks + acbit) ^ axor)) << 4;

    int brow7 = lane & 7;
    int bn8 = (lane >> 4) * 8;
    int bcb = (lane >> 3) & 1;
    int bxor = (brow7 >> 1) & 3;
    uint32_t bBase[2];
#pragma unroll
    for (int p = 0; p < 2; p++)
        bBase[p] =
            sb + A_STAGE + (uint32_t)(wn * 32 + p * 16 + brow7 + bn8) * 64;
    uint32_t boff[2];
#pragma unroll
    for (int ks = 0; ks < 2; ks++)
        boff[ks] = ((uint32_t)((2 * ks + bcb) ^ bxor)) << 4;

    float acc[4][4][4];
#pragma unroll
    for (int i = 0; i < 4; i++)
#pragma unroll
        for (int j = 0; j < 4; j++)
#pragma unroll
            for (int c = 0; c < 4; c++) acc[i][j][c] = 0.f;

    const int T = K / 32;
    LOAD_S128(0, 0);
    LOAD_S128(1, 1);
    LOAD_S128(2, 2);

    for (int t = 0; t < T; t++) {
        int rem = ((t + 2 < T) ? (t + 2) : (T - 1)) - t;
        if (rem == 2)
            asm volatile("cp.async.wait_group 2;");
        else if (rem == 1)
            asm volatile("cp.async.wait_group 1;");
        else
            asm volatile("cp.async.wait_group 0;");
        __syncthreads();
        if (t + 3 < T) LOAD_S128((t + 3) & 3, t + 3);

        uint32_t so = (uint32_t)(t & 3) * G128_STAGE;
        // full-tile fragment prefetch: all LDSMs before any MMA
        uint32_t af[2][4][4], bf[2][4][2];
#pragma unroll
        for (int ks = 0; ks < 2; ks++) {
#pragma unroll
            for (int mf = 0; mf < 4; mf++)
                LDSM_X4(af[ks][mf][0], af[ks][mf][1], af[ks][mf][2],
                        af[ks][mf][3], aBase[mf] + so + aoff[ks]);
#pragma unroll
            for (int p = 0; p < 2; p++)
                LDSM_X4(bf[ks][2 * p][0], bf[ks][2 * p][1],
                        bf[ks][2 * p + 1][0], bf[ks][2 * p + 1][1],
                        bBase[p] + so + boff[ks]);
        }
#pragma unroll
        for (int ks = 0; ks < 2; ks++)
#pragma unroll
            for (int mf = 0; mf < 4; mf++)
#pragma unroll
                for (int nf = 0; nf < 4; nf++)
                    MMA_FP16(acc[mf][nf], af[ks][mf], bf[ks][nf]);
    }

    int r = lane >> 2, kq = lane & 3;
#pragma unroll
    for (int mf = 0; mf < 4; mf++) {
#pragma unroll
        for (int nf = 0; nf < 4; nf++) {
            int n0 = bn + wn * 32 + nf * 8 + kq * 2;
#pragma unroll
            for (int half = 0; half < 2; half++) {
                int m0 = bm + wm * 64 + mf * 16 + r + half * 8;
                float2 v;
                v.x = acc[mf][nf][half * 2 + 0];
                v.y = acc[mf][nf][half * 2 + 1];
                if (flags & FLAG_BIAS) {
                    v.x += bias[n0];
                    v.y += bias[n0 + 1];
                }
                if (flags & FLAG_GELU) {
                    v.x = gelu_tanh(v.x);
                    v.y = gelu_tanh(v.y);
                }
                if (flags & FLAG_HALF) {
                    __half2* dst =
                        (__half2*)((__half*)Cv + (size_t)m0 * Nout + n0);
                    *dst = __floats2half2_rn(v.x, v.y);
                } else {
                    float2* dst =
                        (float2*)((float*)Cv + (size_t)m0 * Nout + n0);
                    *dst = v;
                }
            }
        }
    }
}

// ---------------- flash attention w/ tensor cores (causal + ALiBi) ----------
__global__ __launch_bounds__(128) void attn_mma(const __half* __restrict__ qkv,
                                                __half* __restrict__ out) {
    __shared__ __align__(16) char smem[40960];
    const uint32_t sb = (uint32_t)__cvta_generic_to_shared(smem);
    const int tid = threadIdx.x;
    const int w = tid >> 5, lane = tid & 31;
    const int qt = gridDim.x - 1 - blockIdx.x;
    const int bh = blockIdx.y;
    const int b = bh / NH, h = bh % NH;
    const float slope = c_slopes[h];

    const int srow = tid >> 1, c0 = (tid & 1) * 4;
    const int sxor = srow & 7;
    const uint32_t rowoff = sb + (uint32_t)srow * 128;

    {
        const __half* gQ = qkv +
                           (size_t)(b * Nn + qt * 64 + srow) * QKVW + h * DH +
                           c0 * 8;
#pragma unroll
        for (int i = 0; i < 4; i++)
            cp16(rowoff + (((uint32_t)((c0 + i) ^ sxor)) << 4), gQ + i * 8);
        asm volatile("cp.async.commit_group;");
    }

#define LOAD_KV(kt_, buf_)                                                   \
    do {                                                                     \
        const __half* _gK = qkv +                                            \
                            (size_t)(b * Nn + (kt_)*64 + srow) * QKVW + EMB + \
                            h * DH + c0 * 8;                                 \
        uint32_t _base = rowoff + 8192 + (uint32_t)(buf_)*16384;             \
        _Pragma("unroll") for (int _i = 0; _i < 4; _i++)                     \
            cp16(_base + (((uint32_t)((c0 + _i) ^ sxor)) << 4), _gK + _i * 8); \
        _Pragma("unroll") for (int _i = 0; _i < 4; _i++)                     \
            cp16(_base + 8192 + (((uint32_t)((c0 + _i) ^ sxor)) << 4),       \
                 _gK + EMB + _i * 8);                                        \
        asm volatile("cp.async.commit_group;");                              \
    } while (0)

    LOAD_KV(0, 0);

    asm volatile("cp.async.wait_group 1;");
    __syncthreads();
    const int arow7 = lane & 7;
    const int a8 = ((lane >> 3) & 1) * 8;
    const int acbit = lane >> 4;
    uint32_t Qf[4][4];
    {
        uint32_t qrow = (uint32_t)(w * 16 + arow7 + a8);
        uint32_t qaddr = sb + qrow * 128;
#pragma unroll
        for (int kc = 0; kc < 4; kc++)
            LDSM_X4(Qf[kc][0], Qf[kc][1], Qf[kc][2], Qf[kc][3],
                    qaddr + (((uint32_t)((2 * kc + acbit) ^ arow7)) << 4));
    }

    const int r = lane >> 2, kq = lane & 3;
    const int row0 = qt * 64 + w * 16 + r;
    const int row1 = row0 + 8;
    float m0 = -1e30f, m1 = -1e30f, l0 = 0.f, l1 = 0.f;
    float O[8][4];
#pragma unroll
    for (int dt = 0; dt < 8; dt++)
#pragma unroll
        for (int c = 0; c < 4; c++) O[dt][c] = 0.f;

    const int bg = lane >> 3;
    const int bcb = bg & 1;
    const int brofs = (bg >> 1) * 8;
    const int brow7 = lane & 7;
    const uint32_t vrowlocal = (uint32_t)((lane & 7) + ((lane >> 3) & 1) * 8);
    const int vcbit = lane >> 4;

    for (int kt = 0; kt <= qt; kt++) {
        int buf = kt & 1;
        if (kt < qt) LOAD_KV(kt + 1, buf ^ 1);
        if (kt < qt)
            asm volatile("cp.async.wait_group 1;");
        else
            asm volatile("cp.async.wait_group 0;");
        __syncthreads();

        uint32_t kbase = sb + 8192 + (uint32_t)buf * 16384;
        uint32_t vbase = kbase + 8192;

        float S[8][4];
#pragma unroll
        for (int nt = 0; nt < 8; nt++)
#pragma unroll
            for (int c = 0; c < 4; c++) S[nt][c] = 0.f;
#pragma unroll
        for (int kc = 0; kc < 4; kc++) {
            uint32_t bf[8][2];
#pragma unroll
            for (int p = 0; p < 4; p++) {
                uint32_t rr = (uint32_t)(p * 16 + brofs + brow7);
                LDSM_X4(bf[2 * p][0], bf[2 * p][1], bf[2 * p + 1][0],
                        bf[2 * p + 1][1],
                        kbase + rr * 128 +
                            (((uint32_t)((2 * kc + bcb) ^ brow7)) << 4));
            }
#pragma unroll
            for (int nt = 0; nt < 8; nt++) MMA_FP16(S[nt], Qf[kc], bf[nt]);
        }

        bool diag = (kt == qt);
        float mx0 = -1e30f, mx1 = -1e30f;
#pragma unroll
        for (int nt = 0; nt < 8; nt++) {
            int colb = kt * 64 + nt * 8 + kq * 2;
#pragma unroll
            for (int c = 0; c < 4; c++) {
                int col = colb + (c & 1);
                float v = S[nt][c] * 0.125f + slope * (float)col;
                if (diag && col > ((c < 2) ? row0 : row1)) v = -1e30f;
                S[nt][c] = v;
                if (c < 2)
                    mx0 = fmaxf(mx0, v);
                else
                    mx1 = fmaxf(mx1, v);
            }
        }
        mx0 = fmaxf(mx0, __shfl_xor_sync(0xffffffffu, mx0, 1));
        mx0 = fmaxf(mx0, __shfl_xor_sync(0xffffffffu, mx0, 2));
        mx1 = fmaxf(mx1, __shfl_xor_sync(0xffffffffu, mx1, 1));
        mx1 = fmaxf(mx1, __shfl_xor_sync(0xffffffffu, mx1, 2));

        float nm0 = fmaxf(m0, mx0), nm1 = fmaxf(m1, mx1);
        float corr0 = __expf(m0 - nm0), corr1 = __expf(m1 - nm1);
        m0 = nm0;
        m1 = nm1;

        float sum0 = 0.f, sum1 = 0.f;
#pragma unroll
        for (int nt = 0; nt < 8; nt++) {
            float p0 = __expf(S[nt][0] - m0);
            float p1 = __expf(S[nt][1] - m0);
            float p2 = __expf(S[nt][2] - m1);
            float p3 = __expf(S[nt][3] - m1);
            S[nt][0] = p0;
            S[nt][1] = p1;
            S[nt][2] = p2;
            S[nt][3] = p3;
            sum0 += p0 + p1;
            sum1 += p2 + p3;
        }
        sum0 += __shfl_xor_sync(0xffffffffu, sum0, 1);
        sum0 += __shfl_xor_sync(0xffffffffu, sum0, 2);
        sum1 += __shfl_xor_sync(0xffffffffu, sum1, 1);
        sum1 += __shfl_xor_sync(0xffffffffu, sum1, 2);
        l0 = l0 * corr0 + sum0;
        l1 = l1 * corr1 + sum1;

#pragma unroll
        for (int dt = 0; dt < 8; dt++) {
            O[dt][0] *= corr0;
            O[dt][1] *= corr0;
            O[dt][2] *= corr1;
            O[dt][3] *= corr1;
        }

#pragma unroll
        for (int kc2 = 0; kc2 < 4; kc2++) {
            uint32_t aP[4];
            aP[0] = packh2(S[2 * kc2][0], S[2 * kc2][1]);
            aP[1] = packh2(S[2 * kc2][2], S[2 * kc2][3]);
            aP[2] = packh2(S[2 * kc2 + 1][0], S[2 * kc2 + 1][1]);
            aP[3] = packh2(S[2 * kc2 + 1][2], S[2 * kc2 + 1][3]);
            uint32_t vrow = (uint32_t)(kc2 * 16) + vrowlocal;
            uint32_t vra = vbase + vrow * 128;
            uint32_t vswz = vrow & 7;
#pragma unroll
            for (int cc = 0; cc < 4; cc++) {
                uint32_t v0, v1, v2, v3;
                LDSM_X4_T(v0, v1, v2, v3,
                          vra + (((uint32_t)((2 * cc + vcbit) ^ vswz)) << 4));
                uint32_t bA[2] = {v0, v1}, bB[2] = {v2, v3};
                MMA_FP16(O[2 * cc], aP, bA);
                MMA_FP16(O[2 * cc + 1], aP, bB);
            }
        }
        __syncthreads();
    }

    float i0 = 1.0f / l0, i1 = 1.0f / l1;
    __half* o0 = out + (size_t)(b * Nn + row0) * EMB + h * DH + kq * 2;
    __half* o1 = out + (size_t)(b * Nn + row1) * EMB + h * DH + kq * 2;
#pragma unroll
    for (int dt = 0; dt < 8; dt++) {
        *(__half2*)(o0 + dt * 8) =
            __floats2half2_rn(O[dt][0] * i0, O[dt][1] * i0);
        *(__half2*)(o1 + dt * 8) =
            __floats2half2_rn(O[dt][2] * i1, O[dt][3] * i1);
    }
}

// ---------------- host orchestration -----------------------------------------
extern "C" void kernel_launch(void* const* d_in, const int* in_sizes, int n_in,
                              void* d_out, int out_size) {
    const float* x = (const float*)d_in[0];
    const float* wqkv = (const float*)d_in[1];
    const float* bqkv = (const float*)d_in[2];
    const float* wo = (const float*)d_in[3];
    const float* bo = (const float*)d_in[4];
    const float* ln1s = (const float*)d_in[5];
    const float* ln1b = (const float*)d_in[6];
    const float* ln2s = (const float*)d_in[7];
    const float* ln2b = (const float*)d_in[8];
    const float* w1 = (const float*)d_in[9];
    const float* w2 = (const float*)d_in[10];
    const float* lnfs = (const float*)d_in[11];
    const float* lnfb = (const float*)d_in[12];
    float* out = (float*)d_out;

    float *p_h, *p_part;
    __half *p_y, *p_qkv, *p_o, *p_mid, *p_wqkv, *p_wo, *p_w1, *p_w2;
    cudaGetSymbolAddress((void**)&p_h, g_h);
    cudaGetSymbolAddress((void**)&p_part, g_part);
    cudaGetSymbolAddress((void**)&p_y, g_y);
    cudaGetSymbolAddress((void**)&p_qkv, g_qkv);
    cudaGetSymbolAddress((void**)&p_o, g_o);
    cudaGetSymbolAddress((void**)&p_mid, g_mid);
    cudaGetSymbolAddress((void**)&p_wqkv, g_wqkv);
    cudaGetSymbolAddress((void**)&p_wo, g_wo);
    cudaGetSymbolAddress((void**)&p_w1, g_w1);
    cudaGetSymbolAddress((void**)&p_w2, g_w2);

    cudaFuncSetAttribute(gemm64_sk, cudaFuncAttributeMaxDynamicSharedMemorySize,
                         GEMM_SMEM_64);
    cudaFuncSetAttribute(gemm128, cudaFuncAttributeMaxDynamicSharedMemorySize,
                         GEMM_SMEM_128);

    transpose_half_all<<<TALL, dim3(32, 8)>>>(wqkv, wo, w1, w2, p_wqkv, p_wo,
                                              p_w1, p_w2);

    for (int L = 0; L < DEPTH; L++) {
        if (L == 0)
            ln0_kernel<<<TOK, 192>>>(x, p_h, ln1s, ln1b, p_y);
        else
            ln_fused<<<TOK, 192>>>(p_h, p_part, ln1s + L * EMB, ln1b + L * EMB,
                                   p_y, 1);
        {  // qkv = y @ Wqkv + b (fp16 out)
            dim3 grid(3 * EMB / 128, TOK / 128);
            gemm128<<<grid, 256, GEMM_SMEM_128>>>(
                p_y, p_wqkv + (size_t)L * EMB * 3 * EMB, bqkv + L * 3 * EMB,
                p_qkv, EMB, 3 * EMB, FLAG_BIAS | FLAG_HALF);
        }
        {  // flash attention (heavy tiles first)
            dim3 grid(Nn / 64, Bb * NH);
            attn_mma<<<grid, 128>>>(p_qkv, p_o);
        }
        {  // wo split-K=2 -> partials
            dim3 grid(EMB / 64, TOK / 128, 2);
            gemm64_sk<<<grid, 128, GEMM_SMEM_64>>>(
                p_o, p_wo + (size_t)L * EMB * EMB, p_part, EMB, EMB / 2, EMB);
        }
        ln2_fused<<<TOK, 192>>>(p_h, p_part, bo + L * EMB, ln2s + L * EMB,
                                ln2b + L * EMB, p_y);
        {  // mid = gelu(y @ W1) (half out)
            dim3 grid(FF / 128, TOK / 128);
            gemm128<<<grid, 256, GEMM_SMEM_128>>>(
                p_y, p_w1 + (size_t)L * EMB * FF, nullptr, p_mid, EMB, FF,
                FLAG_GELU | FLAG_HALF);
        }
        {  // w2 split-K=3 -> partials
            dim3 grid(EMB / 64, TOK / 128, 3);
            gemm64_sk<<<grid, 128, GEMM_SMEM_64>>>(
                p_mid, p_w2 + (size_t)L * FF * EMB, p_part, FF, FF / 3, EMB);
        }
    }

    ln_fused<<<TOK, 192>>>(p_h, p_part, lnfs, lnfb, out, 0);
}

// round 17
// speedup vs baseline: 1.1331x; 1.0223x over previous
#include <cuda_runtime.h>
#include <cuda_fp16.h>
#include <math.h>
#include <stdint.h>

#define Bb 2
#define Nn 2048
#define EMB 768
#define NH 12
#define DH 64
#define DEPTH 6
#define FF 3072
#define TOK (Bb * Nn)  // 4096
#define QKVW (3 * EMB) // 2304
#define LN_EPS 1e-6f

// ---------------- scratch (static device globals) ---------------------------
__device__ float g_h[TOK * EMB];
__device__ __half g_y[TOK * EMB];
__device__ __half g_qkv[TOK * 3 * EMB];
__device__ __half g_o[TOK * EMB];
__device__ __half g_mid[TOK * FF];
__device__ float g_part[3 * TOK * EMB];
__device__ __half g_wqkv[DEPTH * EMB * 3 * EMB];
__device__ __half g_wo[DEPTH * EMB * EMB];
__device__ __half g_w1[DEPTH * EMB * FF];
__device__ __half g_w2[DEPTH * FF * EMB];

__constant__ float c_slopes[NH] = {
    0.5f, 0.25f, 0.125f, 0.0625f, 0.03125f, 0.015625f, 0.0078125f, 0.00390625f,
    0.70710678118654752f, 0.35355339059327376f, 0.17677669529663688f,
    0.08838834764831844f};

__device__ __forceinline__ void cp16(uint32_t dst, const void* src) {
    asm volatile("cp.async.cg.shared.global [%0], [%1], 16;" ::"r"(dst),
                 "l"(src));
}

__device__ __forceinline__ uint32_t packh2(float a, float b) {
    __half2 h = __floats2half2_rn(a, b);
    return *(uint32_t*)&h;
}

__device__ __forceinline__ float ex2f(float x) {
    float y;
    asm("ex2.approx.ftz.f32 %0, %1;" : "=f"(y) : "f"(x));
    return y;
}

#define MMA_FP16(d, a, b)                                                     \
    asm volatile(                                                             \
        "mma.sync.aligned.m16n8k16.row.col.f32.f16.f16.f32 "                  \
        "{%0,%1,%2,%3},{%4,%5,%6,%7},{%8,%9},{%0,%1,%2,%3};"                  \
        : "+f"(d[0]), "+f"(d[1]), "+f"(d[2]), "+f"(d[3])                      \
        : "r"(a[0]), "r"(a[1]), "r"(a[2]), "r"(a[3]), "r"(b[0]), "r"(b[1]))

#define LDSM_X4(r0, r1, r2, r3, addr)                                        \
    asm volatile(                                                            \
        "ldmatrix.sync.aligned.m8n8.x4.shared.b16 {%0,%1,%2,%3}, [%4];"      \
        : "=r"(r0), "=r"(r1), "=r"(r2), "=r"(r3)                             \
        : "r"(addr))

#define LDSM_X4_T(r0, r1, r2, r3, addr)                                      \
    asm volatile(                                                            \
        "ldmatrix.sync.aligned.m8n8.x4.trans.shared.b16 {%0,%1,%2,%3}, "     \
        "[%4];"                                                              \
        : "=r"(r0), "=r"(r1), "=r"(r2), "=r"(r3)                             \
        : "r"(addr))

// ---------------- fused transpose + fp16 convert of ALL weights -------------
#define TQKV (72 * 24 * DEPTH)
#define TWO (24 * 24 * DEPTH)
#define TW1 (96 * 24 * DEPTH)
#define TW2 (24 * 96 * DEPTH)
#define TALL (TQKV + TWO + TW1 + TW2)

__global__ void transpose_half_all(const float* __restrict__ wqkv,
                                   const float* __restrict__ wo,
                                   const float* __restrict__ w1,
                                   const float* __restrict__ w2,
                                   __half* __restrict__ pwqkv,
                                   __half* __restrict__ pwo,
                                   __half* __restrict__ pw1,
                                   __half* __restrict__ pw2) {
    __shared__ float tile[32][33];
    int b = blockIdx.x;
    const float* W;
    __half* Wt;
    int K, N;
    if (b < TQKV) {
        W = wqkv; Wt = pwqkv; K = EMB; N = 3 * EMB;
    } else if (b < TQKV + TWO) {
        b -= TQKV; W = wo; Wt = pwo; K = EMB; N = EMB;
    } else if (b < TQKV + TWO + TW1) {
        b -= TQKV + TWO; W = w1; Wt = pw1; K = EMB; N = FF;
    } else {
        b -= TQKV + TWO + TW1; W = w2; Wt = pw2; K = FF; N = EMB;
    }
    int ntiles = N / 32, tpl = ntiles * (K / 32);
    int layer = b / tpl, rem = b % tpl;
    int bn = (rem % ntiles) * 32, bk = (rem / ntiles) * 32;
    W += (size_t)layer * K * N;
    Wt += (size_t)layer * K * N;
    int tx = threadIdx.x, ty = threadIdx.y;
#pragma unroll
    for (int i = 0; i < 32; i += 8)
        tile[ty + i][tx] = W[(size_t)(bk + ty + i) * N + bn + tx];
    __syncthreads();
#pragma unroll
    for (int i = 0; i < 32; i += 8)
        Wt[(size_t)(bn + ty + i) * K + bk + tx] =
            __float2half_rn(tile[tx][ty + i]);
}

// ============== vectorized LayerNorm family (192 threads, float4/thread) ====
__device__ __forceinline__ void block_stats_192(float s, float ss, float& mean,
                                                float& inv) {
#pragma unroll
    for (int of = 16; of; of >>= 1) {
        s += __shfl_xor_sync(0xffffffffu, s, of);
        ss += __shfl_xor_sync(0xffffffffu, ss, of);
    }
    __shared__ float sh_s[8], sh_ss[8];
    int w = threadIdx.x >> 5, lane = threadIdx.x & 31;
    if (lane == 0) { sh_s[w] = s; sh_ss[w] = ss; }
    __syncthreads();
    if (threadIdx.x < 32) {
        s = (lane < 6) ? sh_s[lane] : 0.f;
        ss = (lane < 6) ? sh_ss[lane] : 0.f;
#pragma unroll
        for (int of = 4; of; of >>= 1) {
            s += __shfl_xor_sync(0xffffffffu, s, of);
            ss += __shfl_xor_sync(0xffffffffu, ss, of);
        }
        if (lane == 0) { sh_s[0] = s; sh_ss[0] = ss; }
    }
    __syncthreads();
    mean = sh_s[0] * (1.0f / EMB);
    float var = sh_ss[0] * (1.0f / EMB) - mean * mean;
    inv = rsqrtf(var + LN_EPS);
}

__device__ __forceinline__ void ln_write(float4 v, float mean, float inv,
                                         const float* scale,
                                         const float* bias, void* o, int row,
                                         int i, int half_out) {
    float4 sc = ((const float4*)scale)[i];
    float4 bi = ((const float4*)bias)[i];
    float r0 = (v.x - mean) * inv * sc.x + bi.x;
    float r1 = (v.y - mean) * inv * sc.y + bi.y;
    float r2 = (v.z - mean) * inv * sc.z + bi.z;
    float r3 = (v.w - mean) * inv * sc.w + bi.w;
    if (half_out) {
        uint2 u;
        u.x = packh2(r0, r1);
        u.y = packh2(r2, r3);
        ((uint2*)((__half*)o + (size_t)row * EMB))[i] = u;
    } else {
        float4 r;
        r.x = r0; r.y = r1; r.z = r2; r.w = r3;
        ((float4*)((float*)o + (size_t)row * EMB))[i] = r;
    }
}

// layer-0 LN: reads x, initializes h = x, writes LN(x) -> y (half)
__global__ void ln0_kernel(const float* __restrict__ x,
                           float* __restrict__ h,
                           const float* __restrict__ scale,
                           const float* __restrict__ bias,
                           __half* __restrict__ o) {
    int row = blockIdx.x, i = threadIdx.x;
    float4 v = ((const float4*)(x + (size_t)row * EMB))[i];
    ((float4*)(h + (size_t)row * EMB))[i] = v;
    float mean, inv;
    block_stats_192(v.x + v.y + v.z + v.w,
                    v.x * v.x + v.y * v.y + v.z * v.z + v.w * v.w, mean, inv);
    ln_write(v, mean, inv, scale, bias, o, row, i, 1);
}

// h += p0+p1+p2 (w2 split-K partials), then LN
__global__ void ln_fused(float* __restrict__ h, const float* __restrict__ P,
                         const float* __restrict__ scale,
                         const float* __restrict__ bias, void* __restrict__ o,
                         int half_out) {
    int row = blockIdx.x, i = threadIdx.x;
    float4* hp = (float4*)(h + (size_t)row * EMB);
    const float4* p0 = (const float4*)(P + (size_t)row * EMB);
    const float4* p1 = (const float4*)(P + (size_t)(TOK + row) * EMB);
    const float4* p2 = (const float4*)(P + (size_t)(2 * TOK + row) * EMB);
    float4 v = hp[i], a = p0[i], b = p1[i], c = p2[i];
    v.x += a.x + b.x + c.x;
    v.y += a.y + b.y + c.y;
    v.z += a.z + b.z + c.z;
    v.w += a.w + b.w + c.w;
    hp[i] = v;
    float mean, inv;
    block_stats_192(v.x + v.y + v.z + v.w,
                    v.x * v.x + v.y * v.y + v.z * v.z + v.w * v.w, mean, inv);
    ln_write(v, mean, inv, scale, bias, o, row, i, half_out);
}

// h += p0+p1+bo (wo split-K partials + bias), then LN -> half
__global__ void ln2_fused(float* __restrict__ h, const float* __restrict__ P,
                          const float* __restrict__ bo,
                          const float* __restrict__ scale,
                          const float* __restrict__ bias,
                          __half* __restrict__ o) {
    int row = blockIdx.x, i = threadIdx.x;
    float4* hp = (float4*)(h + (size_t)row * EMB);
    const float4* p0 = (const float4*)(P + (size_t)row * EMB);
    const float4* p1 = (const float4*)(P + (size_t)(TOK + row) * EMB);
    float4 v = hp[i], a = p0[i], b = p1[i];
    float4 bb = ((const float4*)bo)[i];
    v.x += a.x + b.x + bb.x;
    v.y += a.y + b.y + bb.y;
    v.z += a.z + b.z + bb.z;
    v.w += a.w + b.w + bb.w;
    hp[i] = v;
    float mean, inv;
    block_stats_192(v.x + v.y + v.z + v.w,
                    v.x * v.x + v.y * v.y + v.z * v.z + v.w * v.w, mean, inv);
    ln_write(v, mean, inv, scale, bias, o, row, i, 1);
}

#define FLAG_BIAS 1
#define FLAG_GELU 2
#define FLAG_HALF 8

#define STAGES 4
#define A_STAGE 8192

__device__ __forceinline__ float gelu_tanh(float x) {
    const float k0 = 0.7978845608028654f;
    return 0.5f * x * (1.0f + tanhf(k0 * (x + 0.044715f * x * x * x)));
}

// ---------------- split-K gemm: CTA 128x64, z = k-slice, fp32 partial out ---
#define G64_STAGE (A_STAGE + 4096)
#define GEMM_SMEM_64 (STAGES * G64_STAGE)

__global__ __launch_bounds__(128, 4) void gemm64_sk(
    const __half* __restrict__ A, const __half* __restrict__ Wt,
    float* __restrict__ P, int K, int Ksl, int Nout) {
    extern __shared__ char smem[];
    const uint32_t sb = (uint32_t)__cvta_generic_to_shared(smem);
    const int tid = threadIdx.x;
    const int warp = tid >> 5, lane = tid & 31;
    const int wm = warp >> 1, wn = warp & 1;
    const int bm = blockIdx.y * 128, bn = blockIdx.x * 64;
    const int k0 = blockIdx.z * Ksl;
    float* Pz = P + (size_t)blockIdx.z * TOK * EMB;

    const __half* gA = A + (size_t)(bm + tid) * K + k0;
    uint32_t stA[4];
#pragma unroll
    for (int c = 0; c < 4; c++)
        stA[c] = sb + (uint32_t)tid * 64 +
                 (((uint32_t)(c ^ ((tid >> 1) & 3))) << 4);
    const int brow = tid >> 1, bc0 = (tid & 1) * 2;
    const __half* gB = Wt + (size_t)(bn + brow) * K + k0 + bc0 * 8;
    uint32_t stB[2];
#pragma unroll
    for (int i = 0; i < 2; i++)
        stB[i] = sb + A_STAGE + (uint32_t)brow * 64 +
                 (((uint32_t)((bc0 + i) ^ ((brow >> 1) & 3))) << 4);

#define LOAD_S64(s, t_)                                                    \
    do {                                                                   \
        const __half* _a = gA + (t_) * 32;                                 \
        const __half* _b = gB + (t_) * 32;                                 \
        uint32_t _so = (uint32_t)(s)*G64_STAGE;                            \
        _Pragma("unroll") for (int _c = 0; _c < 4; _c++)                   \
            cp16(stA[_c] + _so, _a + _c * 8);                              \
        _Pragma("unroll") for (int _i = 0; _i < 2; _i++)                   \
            cp16(stB[_i] + _so, _b + _i * 8);                              \
        asm volatile("cp.async.commit_group;");                            \
    } while (0)

    int arow7 = lane & 7;
    int a8 = ((lane >> 3) & 1) * 8;
    int acbit = lane >> 4;
    int axor = (arow7 >> 1) & 3;
    uint32_t aBase[4];
#pragma unroll
    for (int mf = 0; mf < 4; mf++)
        aBase[mf] = sb + (uint32_t)(wm * 64 + mf * 16 + arow7 + a8) * 64;
    uint32_t aoff[2];
#pragma unroll
    for (int ks = 0; ks < 2; ks++)
        aoff[ks] = ((uint32_t)((2 * ks + acbit) ^ axor)) << 4;

    int brow7 = lane & 7;
    int bn8 = (lane >> 4) * 8;
    int bcb = (lane >> 3) & 1;
    int bxor = (brow7 >> 1) & 3;
    uint32_t bBase[2];
#pragma unroll
    for (int p = 0; p < 2; p++)
        bBase[p] =
            sb + A_STAGE + (uint32_t)(wn * 32 + p * 16 + brow7 + bn8) * 64;
    uint32_t boff[2];
#pragma unroll
    for (int ks = 0; ks < 2; ks++)
        boff[ks] = ((uint32_t)((2 * ks + bcb) ^ bxor)) << 4;

    float acc[4][4][4];
#pragma unroll
    for (int i = 0; i < 4; i++)
#pragma unroll
        for (int j = 0; j < 4; j++)
#pragma unroll
            for (int c = 0; c < 4; c++) acc[i][j][c] = 0.f;

    const int T = Ksl / 32;
    LOAD_S64(0, 0);
    LOAD_S64(1, 1);
    LOAD_S64(2, 2);

    for (int t = 0; t < T; t++) {
        int rem = ((t + 2 < T) ? (t + 2) : (T - 1)) - t;
        if (rem == 2)
            asm volatile("cp.async.wait_group 2;");
        else if (rem == 1)
            asm volatile("cp.async.wait_group 1;");
        else
            asm volatile("cp.async.wait_group 0;");
        __syncthreads();
        if (t + 3 < T) LOAD_S64((t + 3) & 3, t + 3);

        uint32_t so = (uint32_t)(t & 3) * G64_STAGE;
        uint32_t af[2][4][4], bf[2][4][2];
#pragma unroll
        for (int ks = 0; ks < 2; ks++) {
#pragma unroll
            for (int mf = 0; mf < 4; mf++)
                LDSM_X4(af[ks][mf][0], af[ks][mf][1], af[ks][mf][2],
                        af[ks][mf][3], aBase[mf] + so + aoff[ks]);
#pragma unroll
            for (int p = 0; p < 2; p++)
                LDSM_X4(bf[ks][2 * p][0], bf[ks][2 * p][1],
                        bf[ks][2 * p + 1][0], bf[ks][2 * p + 1][1],
                        bBase[p] + so + boff[ks]);
        }
#pragma unroll
        for (int ks = 0; ks < 2; ks++)
#pragma unroll
            for (int mf = 0; mf < 4; mf++)
#pragma unroll
                for (int nf = 0; nf < 4; nf++)
                    MMA_FP16(acc[mf][nf], af[ks][mf], bf[ks][nf]);
    }

    int r = lane >> 2, kq = lane & 3;
#pragma unroll
    for (int mf = 0; mf < 4; mf++) {
#pragma unroll
        for (int nf = 0; nf < 4; nf++) {
            int n0 = bn + wn * 32 + nf * 8 + kq * 2;
#pragma unroll
            for (int half = 0; half < 2; half++) {
                int m0 = bm + wm * 64 + mf * 16 + r + half * 8;
                float2 v;
                v.x = acc[mf][nf][half * 2 + 0];
                v.y = acc[mf][nf][half * 2 + 1];
                *(float2*)&Pz[(size_t)m0 * Nout + n0] = v;
            }
        }
    }
}

// ---------------- fp16 GEMM, CTA 128x128, 256 thr, KT=32, 2 CTA/SM ----------
#define G128_STAGE (A_STAGE + 8192)
#define GEMM_SMEM_128 (STAGES * G128_STAGE)

__global__ __launch_bounds__(256, 2) void gemm128(
    const __half* __restrict__ A, const __half* __restrict__ Wt,
    const float* __restrict__ bias, void* __restrict__ Cv, int K, int Nout,
    int flags) {
    extern __shared__ char smem[];
    const uint32_t sb = (uint32_t)__cvta_generic_to_shared(smem);
    const int tid = threadIdx.x;
    const int warp = tid >> 5, lane = tid & 31;
    const int wm = warp >> 2, wn = warp & 3;
    const int bm = blockIdx.y * 128, bn = blockIdx.x * 128;

    const int srow = tid >> 1, sc0 = (tid & 1) * 2;
    const __half* gA = A + (size_t)(bm + srow) * K + sc0 * 8;
    const __half* gB = Wt + (size_t)(bn + srow) * K + sc0 * 8;
    uint32_t stA[2], stB[2];
#pragma unroll
    for (int i = 0; i < 2; i++) {
        uint32_t off = (uint32_t)srow * 64 +
                       (((uint32_t)((sc0 + i) ^ ((srow >> 1) & 3))) << 4);
        stA[i] = sb + off;
        stB[i] = sb + A_STAGE + off;
    }

#define LOAD_S128(s, t_)                                                   \
    do {                                                                   \
        const __half* _a = gA + (t_) * 32;                                 \
        const __half* _b = gB + (t_) * 32;                                 \
        uint32_t _so = (uint32_t)(s)*G128_STAGE;                           \
        _Pragma("unroll") for (int _i = 0; _i < 2; _i++) {                 \
            cp16(stA[_i] + _so, _a + _i * 8);                              \
            cp16(stB[_i] + _so, _b + _i * 8);                              \
        }                                                                  \
        asm volatile("cp.async.commit_group;");                            \
    } while (0)

    int arow7 = lane & 7;
    int a8 = ((lane >> 3) & 1) * 8;
    int acbit = lane >> 4;
    int axor = (arow7 >> 1) & 3;
    uint32_t aBase[4];
#pragma unroll
    for (int mf = 0; mf < 4; mf++)
        aBase[mf] = sb + (uint32_t)(wm * 64 + mf * 16 + arow7 + a8) * 64;
    uint32_t aoff[2];
#pragma unroll
    for (int ks = 0; ks < 2; ks++)
        aoff[ks] = ((uint32_t)((2 * ks + acbit) ^ axor)) << 4;

    int brow7 = lane & 7;
    int bn8 = (lane >> 4) * 8;
    int bcb = (lane >> 3) & 1;
    int bxor = (brow7 >> 1) & 3;
    uint32_t bBase[2];
#pragma unroll
    for (int p = 0; p < 2; p++)
        bBase[p] =
            sb + A_STAGE + (uint32_t)(wn * 32 + p * 16 + brow7 + bn8) * 64;
    uint32_t boff[2];
#pragma unroll
    for (int ks = 0; ks < 2; ks++)
        boff[ks] = ((uint32_t)((2 * ks + bcb) ^ bxor)) << 4;

    float acc[4][4][4];
#pragma unroll
    for (int i = 0; i < 4; i++)
#pragma unroll
        for (int j = 0; j < 4; j++)
#pragma unroll
            for (int c = 0; c < 4; c++) acc[i][j][c] = 0.f;

    const int T = K / 32;
    LOAD_S128(0, 0);
    LOAD_S128(1, 1);
    LOAD_S128(2, 2);

    for (int t = 0; t < T; t++) {
        int rem = ((t + 2 < T) ? (t + 2) : (T - 1)) - t;
        if (rem == 2)
            asm volatile("cp.async.wait_group 2;");
        else if (rem == 1)
            asm volatile("cp.async.wait_group 1;");
        else
            asm volatile("cp.async.wait_group 0;");
        __syncthreads();
        if (t + 3 < T) LOAD_S128((t + 3) & 3, t + 3);

        uint32_t so = (uint32_t)(t & 3) * G128_STAGE;
        uint32_t af[2][4][4], bf[2][4][2];
#pragma unroll
        for (int ks = 0; ks < 2; ks++) {
#pragma unroll
            for (int mf = 0; mf < 4; mf++)
                LDSM_X4(af[ks][mf][0], af[ks][mf][1], af[ks][mf][2],
                        af[ks][mf][3], aBase[mf] + so + aoff[ks]);
#pragma unroll
            for (int p = 0; p < 2; p++)
                LDSM_X4(bf[ks][2 * p][0], bf[ks][2 * p][1],
                        bf[ks][2 * p + 1][0], bf[ks][2 * p + 1][1],
                        bBase[p] + so + boff[ks]);
        }
#pragma unroll
        for (int ks = 0; ks < 2; ks++)
#pragma unroll
            for (int mf = 0; mf < 4; mf++)
#pragma unroll
                for (int nf = 0; nf < 4; nf++)
                    MMA_FP16(acc[mf][nf], af[ks][mf], bf[ks][nf]);
    }

    int r = lane >> 2, kq = lane & 3;
#pragma unroll
    for (int mf = 0; mf < 4; mf++) {
#pragma unroll
        for (int nf = 0; nf < 4; nf++) {
            int n0 = bn + wn * 32 + nf * 8 + kq * 2;
#pragma unroll
            for (int half = 0; half < 2; half++) {
                int m0 = bm + wm * 64 + mf * 16 + r + half * 8;
                float2 v;
                v.x = acc[mf][nf][half * 2 + 0];
                v.y = acc[mf][nf][half * 2 + 1];
                if (flags & FLAG_BIAS) {
                    v.x += bias[n0];
                    v.y += bias[n0 + 1];
                }
                if (flags & FLAG_GELU) {
                    v.x = gelu_tanh(v.x);
                    v.y = gelu_tanh(v.y);
                }
                if (flags & FLAG_HALF) {
                    __half2* dst =
                        (__half2*)((__half*)Cv + (size_t)m0 * Nout + n0);
                    *dst = __floats2half2_rn(v.x, v.y);
                } else {
                    float2* dst =
                        (float2*)((float*)Cv + (size_t)m0 * Nout + n0);
                    *dst = v;
                }
            }
        }
    }
}

// ---------------- flash attention, log2-domain softmax ----------------------
__global__ __launch_bounds__(128, 4) void attn_mma(
    const __half* __restrict__ qkv, __half* __restrict__ out) {
    __shared__ __align__(16) char smem[40960];
    const uint32_t sb = (uint32_t)__cvta_generic_to_shared(smem);
    const int tid = threadIdx.x;
    const int w = tid >> 5, lane = tid & 31;
    const int qt = gridDim.x - 1 - blockIdx.x;
    const int bh = blockIdx.y;
    const int b = bh / NH, h = bh % NH;
    const float LOG2E = 1.4426950408889634f;
    const float SC = 0.125f * LOG2E;          // score scale in log2 domain
    const float sl2 = c_slopes[h] * LOG2E;    // alibi slope in log2 domain

    const int srow = tid >> 1, c0 = (tid & 1) * 4;
    const int sxor = srow & 7;
    const uint32_t rowoff = sb + (uint32_t)srow * 128;

    {
        const __half* gQ = qkv +
                           (size_t)(b * Nn + qt * 64 + srow) * QKVW + h * DH +
                           c0 * 8;
#pragma unroll
        for (int i = 0; i < 4; i++)
            cp16(rowoff + (((uint32_t)((c0 + i) ^ sxor)) << 4), gQ + i * 8);
        asm volatile("cp.async.commit_group;");
    }

#define LOAD_KV(kt_, buf_)                                                   \
    do {                                                                     \
        const __half* _gK = qkv +                                            \
                            (size_t)(b * Nn + (kt_)*64 + srow) * QKVW + EMB + \
                            h * DH + c0 * 8;                                 \
        uint32_t _base = rowoff + 8192 + (uint32_t)(buf_)*16384;             \
        _Pragma("unroll") for (int _i = 0; _i < 4; _i++)                     \
            cp16(_base + (((uint32_t)((c0 + _i) ^ sxor)) << 4), _gK + _i * 8); \
        _Pragma("unroll") for (int _i = 0; _i < 4; _i++)                     \
            cp16(_base + 8192 + (((uint32_t)((c0 + _i) ^ sxor)) << 4),       \
                 _gK + EMB + _i * 8);                                        \
        asm volatile("cp.async.commit_group;");                              \
    } while (0)

    LOAD_KV(0, 0);

    asm volatile("cp.async.wait_group 1;");
    __syncthreads();
    const int arow7 = lane & 7;
    const int a8 = ((lane >> 3) & 1) * 8;
    const int acbit = lane >> 4;
    uint32_t Qf[4][4];
    {
        uint32_t qrow = (uint32_t)(w * 16 + arow7 + a8);
        uint32_t qaddr = sb + qrow * 128;
#pragma unroll
        for (int kc = 0; kc < 4; kc++)
            LDSM_X4(Qf[kc][0], Qf[kc][1], Qf[kc][2], Qf[kc][3],
                    qaddr + (((uint32_t)((2 * kc + acbit) ^ arow7)) << 4));
    }

    const int r = lane >> 2, kq = lane & 3;
    const int row0 = qt * 64 + w * 16 + r;
    const int row1 = row0 + 8;
    float m0 = -1e30f, m1 = -1e30f, l0 = 0.f, l1 = 0.f;
    float O[8][4];
#pragma unroll
    for (int dt = 0; dt < 8; dt++)
#pragma unroll
        for (int c = 0; c < 4; c++) O[dt][c] = 0.f;

    const int bg = lane >> 3;
    const int bcb = bg & 1;
    const int brofs = (bg >> 1) * 8;
    const int brow7 = lane & 7;
    const uint32_t vrowlocal = (uint32_t)((lane & 7) + ((lane >> 3) & 1) * 8);
    const int vcbit = lane >> 4;

    for (int kt = 0; kt <= qt; kt++) {
        int buf = kt & 1;
        asm volatile("cp.async.wait_group 0;");
        __syncthreads();
        if (kt < qt) LOAD_KV(kt + 1, buf ^ 1);

        uint32_t kbase = sb + 8192 + (uint32_t)buf * 16384;
        uint32_t vbase = kbase + 8192;

        float S[8][4];
#pragma unroll
        for (int nt = 0; nt < 8; nt++)
#pragma unroll
            for (int c = 0; c < 4; c++) S[nt][c] = 0.f;
#pragma unroll
        for (int kc = 0; kc < 4; kc++) {
            uint32_t bf[8][2];
#pragma unroll
            for (int p = 0; p < 4; p++) {
                uint32_t rr = (uint32_t)(p * 16 + brofs + brow7);
                LDSM_X4(bf[2 * p][0], bf[2 * p][1], bf[2 * p + 1][0],
                        bf[2 * p + 1][1],
                        kbase + rr * 128 +
                            (((uint32_t)((2 * kc + bcb) ^ brow7)) << 4));
            }
#pragma unroll
            for (int nt = 0; nt < 8; nt++) MMA_FP16(S[nt], Qf[kc], bf[nt]);
        }

        // ---- scale + alibi (log2 domain), causal only on diag tile --------
        float mx0 = -1e30f, mx1 = -1e30f;
        if (kt == qt) {
#pragma unroll
            for (int nt = 0; nt < 8; nt++) {
                int colb = kt * 64 + nt * 8 + kq * 2;
                float cb0 = sl2 * (float)colb;
                float cb1 = cb0 + sl2;
                float v0 = fmaf(S[nt][0], SC, cb0);
                float v1 = fmaf(S[nt][1], SC, cb1);
                float v2 = fmaf(S[nt][2], SC, cb0);
                float v3 = fmaf(S[nt][3], SC, cb1);
                if (colb > row0) v0 = -1e30f;
                if (colb + 1 > row0) v1 = -1e30f;
                if (colb > row1) v2 = -1e30f;
                if (colb + 1 > row1) v3 = -1e30f;
                S[nt][0] = v0;
                S[nt][1] = v1;
                S[nt][2] = v2;
                S[nt][3] = v3;
                mx0 = fmaxf(mx0, fmaxf(v0, v1));
                mx1 = fmaxf(mx1, fmaxf(v2, v3));
            }
        } else {
#pragma unroll
            for (int nt = 0; nt < 8; nt++) {
                int colb = kt * 64 + nt * 8 + kq * 2;
                float cb0 = sl2 * (float)colb;
                float cb1 = cb0 + sl2;
                float v0 = fmaf(S[nt][0], SC, cb0);
                float v1 = fmaf(S[nt][1], SC, cb1);
                float v2 = fmaf(S[nt][2], SC, cb0);
                float v3 = fmaf(S[nt][3], SC, cb1);
                S[nt][0] = v0;
                S[nt][1] = v1;
                S[nt][2] = v2;
                S[nt][3] = v3;
                mx0 = fmaxf(mx0, fmaxf(v0, v1));
                mx1 = fmaxf(mx1, fmaxf(v2, v3));
            }
        }
        mx0 = fmaxf(mx0, __shfl_xor_sync(0xffffffffu, mx0, 1));
        mx0 = fmaxf(mx0, __shfl_xor_sync(0xffffffffu, mx0, 2));
        mx1 = fmaxf(mx1, __shfl_xor_sync(0xffffffffu, mx1, 1));
        mx1 = fmaxf(mx1, __shfl_xor_sync(0xffffffffu, mx1, 2));

        float nm0 = fmaxf(m0, mx0), nm1 = fmaxf(m1, mx1);
        float corr0 = ex2f(m0 - nm0), corr1 = ex2f(m1 - nm1);
        m0 = nm0;
        m1 = nm1;

        float sum0 = 0.f, sum1 = 0.f;
#pragma unroll
        for (int nt = 0; nt < 8; nt++) {
            float p0 = ex2f(S[nt][0] - m0);
            float p1 = ex2f(S[nt][1] - m0);
            float p2 = ex2f(S[nt][2] - m1);
            float p3 = ex2f(S[nt][3] - m1);
            S[nt][0] = p0;
            S[nt][1] = p1;
            S[nt][2] = p2;
            S[nt][3] = p3;
            sum0 += p0 + p1;
            sum1 += p2 + p3;
        }
        sum0 += __shfl_xor_sync(0xffffffffu, sum0, 1);
        sum0 += __shfl_xor_sync(0xffffffffu, sum0, 2);
        sum1 += __shfl_xor_sync(0xffffffffu, sum1, 1);
        sum1 += __shfl_xor_sync(0xffffffffu, sum1, 2);
        l0 = l0 * corr0 + sum0;
        l1 = l1 * corr1 + sum1;

#pragma unroll
        for (int dt = 0; dt < 8; dt++) {
            O[dt][0] *= corr0;
            O[dt][1] *= corr0;
            O[dt][2] *= corr1;
            O[dt][3] *= corr1;
        }

#pragma unroll
        for (int kc2 = 0; kc2 < 4; kc2++) {
            uint32_t aP[4];
            aP[0] = packh2(S[2 * kc2][0], S[2 * kc2][1]);
            aP[1] = packh2(S[2 * kc2][2], S[2 * kc2][3]);
            aP[2] = packh2(S[2 * kc2 + 1][0], S[2 * kc2 + 1][1]);
            aP[3] = packh2(S[2 * kc2 + 1][2], S[2 * kc2 + 1][3]);
            uint32_t vrow = (uint32_t)(kc2 * 16) + vrowlocal;
            uint32_t vra = vbase + vrow * 128;
            uint32_t vswz = vrow & 7;
#pragma unroll
            for (int cc = 0; cc < 4; cc++) {
                uint32_t v0, v1, v2, v3;
                LDSM_X4_T(v0, v1, v2, v3,
                          vra + (((uint32_t)((2 * cc + vcbit) ^ vswz)) << 4));
                uint32_t bA[2] = {v0, v1}, bB[2] = {v2, v3};
                MMA_FP16(O[2 * cc], aP, bA);
                MMA_FP16(O[2 * cc + 1], aP, bB);
            }
        }
    }

    float i0 = 1.0f / l0, i1 = 1.0f / l1;
    __half* o0 = out + (size_t)(b * Nn + row0) * EMB + h * DH + kq * 2;
    __half* o1 = out + (size_t)(b * Nn + row1) * EMB + h * DH + kq * 2;
#pragma unroll
    for (int dt = 0; dt < 8; dt++) {
        *(__half2*)(o0 + dt * 8) =
            __floats2half2_rn(O[dt][0] * i0, O[dt][1] * i0);
        *(__half2*)(o1 + dt * 8) =
            __floats2half2_rn(O[dt][2] * i1, O[dt][3] * i1);
    }
}

// ---------------- host orchestration -----------------------------------------
extern "C" void kernel_launch(void* const* d_in, const int* in_sizes, int n_in,
                              void* d_out, int out_size) {
    const float* x = (const float*)d_in[0];
    const float* wqkv = (const float*)d_in[1];
    const float* bqkv = (const float*)d_in[2];
    const float* wo = (const float*)d_in[3];
    const float* bo = (const float*)d_in[4];
    const float* ln1s = (const float*)d_in[5];
    const float* ln1b = (const float*)d_in[6];
    const float* ln2s = (const float*)d_in[7];
    const float* ln2b = (const float*)d_in[8];
    const float* w1 = (const float*)d_in[9];
    const float* w2 = (const float*)d_in[10];
    const float* lnfs = (const float*)d_in[11];
    const float* lnfb = (const float*)d_in[12];
    float* out = (float*)d_out;

    float *p_h, *p_part;
    __half *p_y, *p_qkv, *p_o, *p_mid, *p_wqkv, *p_wo, *p_w1, *p_w2;
    cudaGetSymbolAddress((void**)&p_h, g_h);
    cudaGetSymbolAddress((void**)&p_part, g_part);
    cudaGetSymbolAddress((void**)&p_y, g_y);
    cudaGetSymbolAddress((void**)&p_qkv, g_qkv);
    cudaGetSymbolAddress((void**)&p_o, g_o);
    cudaGetSymbolAddress((void**)&p_mid, g_mid);
    cudaGetSymbolAddress((void**)&p_wqkv, g_wqkv);
    cudaGetSymbolAddress((void**)&p_wo, g_wo);
    cudaGetSymbolAddress((void**)&p_w1, g_w1);
    cudaGetSymbolAddress((void**)&p_w2, g_w2);

    cudaFuncSetAttribute(gemm64_sk, cudaFuncAttributeMaxDynamicSharedMemorySize,
                         GEMM_SMEM_64);
    cudaFuncSetAttribute(gemm128, cudaFuncAttributeMaxDynamicSharedMemorySize,
                         GEMM_SMEM_128);

    transpose_half_all<<<TALL, dim3(32, 8)>>>(wqkv, wo, w1, w2, p_wqkv, p_wo,
                                              p_w1, p_w2);

    for (int L = 0; L < DEPTH; L++) {
        if (L == 0)
            ln0_kernel<<<TOK, 192>>>(x, p_h, ln1s, ln1b, p_y);
        else
            ln_fused<<<TOK, 192>>>(p_h, p_part, ln1s + L * EMB, ln1b + L * EMB,
                                   p_y, 1);
        {  // qkv = y @ Wqkv + b (fp16 out)
            dim3 grid(3 * EMB / 128, TOK / 128);
            gemm128<<<grid, 256, GEMM_SMEM_128>>>(
                p_y, p_wqkv + (size_t)L * EMB * 3 * EMB, bqkv + L * 3 * EMB,
                p_qkv, EMB, 3 * EMB, FLAG_BIAS | FLAG_HALF);
        }
        {  // flash attention (heavy tiles first)
            dim3 grid(Nn / 64, Bb * NH);
            attn_mma<<<grid, 128>>>(p_qkv, p_o);
        }
        {  // wo split-K=2 -> partials
            dim3 grid(EMB / 64, TOK / 128, 2);
            gemm64_sk<<<grid, 128, GEMM_SMEM_64>>>(
                p_o, p_wo + (size_t)L * EMB * EMB, p_part, EMB, EMB / 2, EMB);
        }
        ln2_fused<<<TOK, 192>>>(p_h, p_part, bo + L * EMB, ln2s + L * EMB,
                                ln2b + L * EMB, p_y);
        {  // mid = gelu(y @ W1) (half out)
            dim3 grid(FF / 128, TOK / 128);
            gemm128<<<grid, 256, GEMM_SMEM_128>>>(
                p_y, p_w1 + (size_t)L * EMB * FF, nullptr, p_mid, EMB, FF,
                FLAG_GELU | FLAG_HALF);
        }
        {  // w2 split-K=3 -> partials
            dim3 grid(EMB / 64, TOK / 128, 3);
            gemm64_sk<<<grid, 128, GEMM_SMEM_64>>>(
                p_mid, p_w2 + (size_t)L * FF * EMB, p_part, FF, FF / 3, EMB);
        }
    }

    ln_fused<<<TOK, 192>>>(p_h, p_part, lnfs, lnfb, out, 0);
}